// round 11
// baseline (speedup 1.0000x reference)
#include <cuda_runtime.h>
#include <math.h>

#define D_ 128
#define NMAX 50016
#define EPMAX 550032
#define MAXN 0.99999f
#define MINNORM 1e-15f

// ---------------- scratch ----------------
__device__ float g_xe[NMAX * D_];
__device__ float g_xh[NMAX * D_];
__device__ float g_lx[NMAX * D_];
__device__ float g_agg_e[NMAX * D_];
__device__ float g_agg_h[NMAX * D_];
__device__ float g_ai[NMAX * 4];
__device__ float g_aj[NMAX * 4];
__device__ float g_hi[NMAX * 4];
__device__ float g_hj[NMAX * 4];
__device__ float g_x2[NMAX];
__device__ float g_de[EPMAX];       // exp(distance)
__device__ float g_WtE[D_ * D_];
__device__ float g_WtH[D_ * D_];
__device__ int   g_deg[NMAX];
__device__ int   g_cur[NMAX];
__device__ int   g_start[NMAX + 1];
__device__ int   g_csrc[EPMAX];
__device__ int   g_bsum[256];

// ---------------- helpers ----------------
__device__ __forceinline__ float atanhc(float x) {
    x = fminf(fmaxf(x, -1.0f + 1e-7f), 1.0f - 1e-7f);
    return atanhf(x);
}
__device__ __forceinline__ float wsum(float v) {
#pragma unroll
    for (int o = 16; o; o >>= 1) v += __shfl_xor_sync(0xffffffffu, v, o);
    return v;
}
__device__ __forceinline__ float d4(float4 a, float4 b) {
    return a.x * b.x + a.y * b.y + a.z * b.z + a.w * b.w;
}
__device__ __forceinline__ float4 f4s(float4 a, float s) {
    return make_float4(a.x * s, a.y * s, a.z * s, a.w * s);
}
__device__ __forceinline__ float4 f4axby(float a, float4 x, float b, float4 y) {
    return make_float4(a * x.x + b * y.x, a * x.y + b * y.y,
                       a * x.z + b * y.z, a * x.w + b * y.w);
}
__device__ __forceinline__ float lrelu(float v) { return v >= 0.f ? v : 0.2f * v; }

// packed f32x2 helpers (Blackwell FFMA2)
__device__ __forceinline__ void ffma2(unsigned long long &acc,
                                      unsigned long long a, unsigned long long b) {
    asm("fma.rn.f32x2 %0, %1, %2, %3;" : "=l"(acc) : "l"(a), "l"(b), "l"(acc));
}
__device__ __forceinline__ unsigned long long pack2(float s) {
    unsigned u = __float_as_uint(s);
    unsigned long long r;
    asm("mov.b64 %0, {%1, %1};" : "=l"(r) : "r"(u));
    return r;
}
__device__ __forceinline__ float4 unpack4(unsigned long long lo, unsigned long long hi) {
    float4 v;
    asm("mov.b64 {%0, %1}, %2;" : "=f"(v.x), "=f"(v.y) : "l"(lo));
    asm("mov.b64 {%0, %1}, %2;" : "=f"(v.z), "=f"(v.w) : "l"(hi));
    return v;
}

// ---------------- init: zero degrees + transpose weights ----------------
__global__ __launch_bounds__(256) void init_kernel(const float* __restrict__ We,
                                                   const float* __restrict__ Wh, int N) {
    int i = blockIdx.x * blockDim.x + threadIdx.x;
    if (i < N) g_deg[i] = 0;
    if (i < 2 * D_ * D_) {
        int m = i >> 14;
        int k = (i >> 7) & 127;
        int c = i & 127;
        if (m == 0) g_WtE[k * D_ + c] = We[c * D_ + k];
        else        g_WtH[k * D_ + c] = Wh[c * D_ + k];
    }
}

__global__ __launch_bounds__(256) void count_kernel(const int* __restrict__ ei, int E, int EP) {
    int e = blockIdx.x * blockDim.x + threadIdx.x;
    if (e >= EP) return;
    int dn = (e < E) ? ei[E + e] : (e - E);
    atomicAdd(&g_deg[dn], 1);
}

__global__ __launch_bounds__(256) void scan1_kernel(int N) {
    __shared__ int sm[256];
    int i = blockIdx.x * 256 + threadIdx.x;
    int v = (i < N) ? g_deg[i] : 0;
    sm[threadIdx.x] = v;
    __syncthreads();
#pragma unroll
    for (int d = 1; d < 256; d <<= 1) {
        int t = (threadIdx.x >= d) ? sm[threadIdx.x - d] : 0;
        __syncthreads();
        sm[threadIdx.x] += t;
        __syncthreads();
    }
    if (i < N) g_start[i] = sm[threadIdx.x] - v;
    if (threadIdx.x == 255) g_bsum[blockIdx.x] = sm[255];
}

__global__ __launch_bounds__(256) void scan2_kernel(int nb) {
    __shared__ int sm[256];
    int v = (threadIdx.x < nb) ? g_bsum[threadIdx.x] : 0;
    sm[threadIdx.x] = v;
    __syncthreads();
#pragma unroll
    for (int d = 1; d < 256; d <<= 1) {
        int t = (threadIdx.x >= d) ? sm[threadIdx.x - d] : 0;
        __syncthreads();
        sm[threadIdx.x] += t;
        __syncthreads();
    }
    g_bsum[threadIdx.x] = sm[threadIdx.x] - v;
}

__global__ __launch_bounds__(256) void scan3_kernel(int N, int EP) {
    int i = blockIdx.x * 256 + threadIdx.x;
    if (i < N) { g_start[i] += g_bsum[i >> 8]; g_cur[i] = 0; }
    if (i == 0) g_start[N] = EP;
}

__global__ __launch_bounds__(256) void scatter_kernel(const int* __restrict__ ei, int E, int EP) {
    int e = blockIdx.x * blockDim.x + threadIdx.x;
    if (e >= EP) return;
    int s, dn;
    if (e < E) { s = ei[e]; dn = ei[E + e]; } else { s = dn = e - E; }
    int pos = atomicAdd(&g_cur[dn], 1);
    g_csrc[g_start[dn] + pos] = s;
}

// ---------------- node kernels: 8 nodes/warp ----------------
__global__ __launch_bounds__(128) void node_e_kernel(const float* __restrict__ x,
                                                     const float* __restrict__ b_lin,
                                                     const float* __restrict__ att,
                                                     int N) {
    __shared__ float sx[4][8][D_];
    int w = threadIdx.x >> 5, l = threadIdx.x & 31;
    int base = blockIdx.x * 32 + w * 8;
    if (base >= N) return;
#pragma unroll
    for (int j = 0; j < 8; j++) {
        int n = min(base + j, N - 1);
        ((float4*)sx[w][j])[l] = ((const float4*)x)[n * 32 + l];
    }
    __syncwarp();
    unsigned long long acc[8][2];
#pragma unroll
    for (int j = 0; j < 8; j++) { acc[j][0] = 0ull; acc[j][1] = 0ull; }
    const ulonglong2* Wt = (const ulonglong2*)g_WtE;
#pragma unroll 2
    for (int k = 0; k < D_; k++) {
        ulonglong2 wv = Wt[k * 32 + l];
#pragma unroll
        for (int j = 0; j < 8; j++) {
            unsigned long long ss = pack2(sx[w][j][k]);
            ffma2(acc[j][0], ss, wv.x);
            ffma2(acc[j][1], ss, wv.y);
        }
    }
    float4 bv = ((const float4*)b_lin)[l];
    int h = l >> 3, j0 = (l & 7) * 4;
    const float* at  = att + h * 64 + j0;
    const float* at2 = at + 32;
#pragma unroll
    for (int j = 0; j < 8; j++) {
        int n = base + j;
        if (n >= N) break;
        float4 a = unpack4(acc[j][0], acc[j][1]);
        a.x += bv.x; a.y += bv.y; a.z += bv.z; a.w += bv.w;
        ((float4*)g_xe)[n * 32 + l] = a;
        float pi = a.x * at[0]  + a.y * at[1]  + a.z * at[2]  + a.w * at[3];
        float pj = a.x * at2[0] + a.y * at2[1] + a.z * at2[2] + a.w * at2[3];
#pragma unroll
        for (int o = 4; o; o >>= 1) {
            pi += __shfl_down_sync(0xffffffffu, pi, o, 8);
            pj += __shfl_down_sync(0xffffffffu, pj, o, 8);
        }
        if ((l & 7) == 0) { g_ai[n * 4 + h] = pi; g_aj[n * 4 + h] = pj; }
    }
}

__global__ __launch_bounds__(128) void node_h_kernel(const float* __restrict__ x,
                                                     const float* __restrict__ b_lin,
                                                     const float* __restrict__ att,
                                                     int N) {
    __shared__ float sx[4][8][D_];
    int w = threadIdx.x >> 5, l = threadIdx.x & 31;
    int base = blockIdx.x * 32 + w * 8;
    if (base >= N) return;
    float pnx[8];
#pragma unroll
    for (int j = 0; j < 8; j++) {
        int n = min(base + j, N - 1);
        float4 xv = ((const float4*)x)[n * 32 + l];
        ((float4*)sx[w][j])[l] = xv;
        pnx[j] = d4(xv, xv);
    }
#pragma unroll
    for (int o = 16; o; o >>= 1) {
#pragma unroll
        for (int j = 0; j < 8; j++) pnx[j] += __shfl_xor_sync(0xffffffffu, pnx[j], o);
    }
    __syncwarp();
    unsigned long long acc[8][2];
#pragma unroll
    for (int j = 0; j < 8; j++) { acc[j][0] = 0ull; acc[j][1] = 0ull; }
    const ulonglong2* Wt = (const ulonglong2*)g_WtH;
#pragma unroll 2
    for (int k = 0; k < D_; k++) {
        ulonglong2 wv = Wt[k * 32 + l];
#pragma unroll
        for (int j = 0; j < 8; j++) {
            unsigned long long ss = pack2(sx[w][j][k]);
            ffma2(acc[j][0], ss, wv.x);
            ffma2(acc[j][1], ss, wv.y);
        }
    }
    float4 bvv = ((const float4*)b_lin)[l];
    float nb = fmaxf(sqrtf(wsum(d4(bvv, bvv))), MINNORM);
    float nhb = fminf(tanhf(nb), MAXN);
    float4 hb = f4s(bvv, nhb / nb);
    float y2 = nhb * nhb;

    float4 mx[8];
    float pm[8];
#pragma unroll
    for (int j = 0; j < 8; j++) {
        mx[j] = unpack4(acc[j][0], acc[j][1]);
        pm[j] = d4(mx[j], mx[j]);
    }
#pragma unroll
    for (int o = 16; o; o >>= 1) {
#pragma unroll
        for (int j = 0; j < 8; j++) pm[j] += __shfl_xor_sync(0xffffffffu, pm[j], o);
    }
    float nmv[8];
#pragma unroll
    for (int j = 0; j < 8; j++) {
        float n_x = fmaxf(sqrtf(pnx[j]), MINNORM);
        float n_mx = fmaxf(sqrtf(pm[j]), MINNORM);
        nmv[j] = fminf(tanhf(n_mx / n_x * atanhc(n_x)), MAXN);
        float s = nmv[j] / n_mx;
        mx[j] = f4s(mx[j], s);
    }
    float pxy[8];
#pragma unroll
    for (int j = 0; j < 8; j++) pxy[j] = d4(mx[j], hb);
#pragma unroll
    for (int o = 16; o; o >>= 1) {
#pragma unroll
        for (int j = 0; j < 8; j++) pxy[j] += __shfl_xor_sync(0xffffffffu, pxy[j], o);
    }

    int h = l >> 3, j0 = (l & 7) * 4;
    const float* at  = att + h * 64 + j0;
    const float* at2 = at + 32;
#pragma unroll
    for (int j = 0; j < 8; j++) {
        int n = base + j;
        if (n >= N) break;
        float x2 = nmv[j] * nmv[j];
        float xy = pxy[j];
        float A = 1.f + 2.f * xy + y2, B = 1.f - x2;
        float den = fmaxf(1.f + 2.f * xy + x2 * y2, MINNORM);
        float invden = 1.f / den;
        float nxh2 = fmaxf(A * A * x2 + 2.f * A * B * xy + B * B * y2, 0.f)
                     * invden * invden;
        float nxh = fmaxf(sqrtf(nxh2), MINNORM);
        float c = (nxh > MAXN) ? (MAXN / nxh) : 1.f;
        float4 xh = f4s(f4axby(A, mx[j], B, hb), invden * c);
        float nfin = c * nxh;
        float x2f = nfin * nfin;
        ((float4*)g_xh)[n * 32 + l] = xh;
        if (l == 0) g_x2[n] = x2f;
        float ncl = fmaxf(nfin, MINNORM);
        float4 lx = f4s(xh, atanhc(ncl) / ncl);
        ((float4*)g_lx)[n * 32 + l] = lx;
        float pi = lx.x * at[0]  + lx.y * at[1]  + lx.z * at[2]  + lx.w * at[3];
        float pj = lx.x * at2[0] + lx.y * at2[1] + lx.z * at2[2] + lx.w * at2[3];
#pragma unroll
        for (int o = 4; o; o >>= 1) {
            pi += __shfl_down_sync(0xffffffffu, pi, o, 8);
            pj += __shfl_down_sync(0xffffffffu, pj, o, 8);
        }
        if ((l & 7) == 0) { g_hi[n * 4 + h] = pi; g_hj[n * 4 + h] = pj; }
    }
}

// ---------------- edge kernel (passes A+B only; stores normalized aggregates) ----------------
__global__ __launch_bounds__(256) void edge_kernel(int N) {
    int w = (blockIdx.x * blockDim.x + threadIdx.x) >> 5;
    int l = threadIdx.x & 31;
    if (w >= N) return;
    int dn = w;
    int beg = g_start[dn], end = g_start[dn + 1];
    int h = l >> 3;
    bool leader = (l & 7) == 0;

    float4 xd  = ((const float4*)g_xh)[dn * 32 + l];
    float  x2d = g_x2[dn];
    float  ai_l = g_ai[dn * 4 + h];
    float  hi_l = g_hi[dn * 4 + h];

    // ---- Pass A: distances + euclid softmax-weighted aggregation (masked x4) ----
    float sum_d = 0.f, sum_e = 0.f;
    float4 acc_e = make_float4(0.f, 0.f, 0.f, 0.f);
    for (int k = beg; k < end; k += 4) {
        int k1 = min(k + 1, end - 1), k2 = min(k + 2, end - 1), k3 = min(k + 3, end - 1);
        float m1 = (k + 1 < end) ? 1.f : 0.f;
        float m2 = (k + 2 < end) ? 1.f : 0.f;
        float m3 = (k + 3 < end) ? 1.f : 0.f;
        int s0 = g_csrc[k], s1 = g_csrc[k1], s2 = g_csrc[k2], s3 = g_csrc[k3];
        float4 v0 = ((const float4*)g_xh)[s0 * 32 + l];
        float4 v1 = ((const float4*)g_xh)[s1 * 32 + l];
        float4 v2 = ((const float4*)g_xh)[s2 * 32 + l];
        float4 v3 = ((const float4*)g_xh)[s3 * 32 + l];
        float4 e0 = ((const float4*)g_xe)[s0 * 32 + l];
        float4 e1 = ((const float4*)g_xe)[s1 * 32 + l];
        float4 e2 = ((const float4*)g_xe)[s2 * 32 + l];
        float4 e3 = ((const float4*)g_xe)[s3 * 32 + l];
        float le0 = __expf(lrelu(ai_l + g_aj[s0 * 4 + h]));
        float le1 = __expf(lrelu(ai_l + g_aj[s1 * 4 + h])) * m1;
        float le2 = __expf(lrelu(ai_l + g_aj[s2 * 4 + h])) * m2;
        float le3 = __expf(lrelu(ai_l + g_aj[s3 * 4 + h])) * m3;
        acc_e.x = fmaf(le0, e0.x, fmaf(le1, e1.x, fmaf(le2, e2.x, fmaf(le3, e3.x, acc_e.x))));
        acc_e.y = fmaf(le0, e0.y, fmaf(le1, e1.y, fmaf(le2, e2.y, fmaf(le3, e3.y, acc_e.y))));
        acc_e.z = fmaf(le0, e0.z, fmaf(le1, e1.z, fmaf(le2, e2.z, fmaf(le3, e3.z, acc_e.z))));
        acc_e.w = fmaf(le0, e0.w, fmaf(le1, e1.w, fmaf(le2, e2.w, fmaf(le3, e3.w, acc_e.w))));
        if (leader) sum_e += le0 + le1 + le2 + le3;
        float p0 = d4(xd, v0), p1 = d4(xd, v1), p2 = d4(xd, v2), p3 = d4(xd, v3);
#pragma unroll
        for (int o = 16; o; o >>= 1) {
            p0 += __shfl_xor_sync(0xffffffffu, p0, o);
            p1 += __shfl_xor_sync(0xffffffffu, p1, o);
            p2 += __shfl_xor_sync(0xffffffffu, p2, o);
            p3 += __shfl_xor_sync(0xffffffffu, p3, o);
        }
        if (l < 4 && k + l < end) {
            int ssel = (l == 0) ? s0 : (l == 1) ? s1 : (l == 2) ? s2 : s3;
            float pp = (l == 0) ? p0 : (l == 1) ? p1 : (l == 2) ? p2 : p3;
            float yy = g_x2[ssel];
            float A = 1.f - 2.f * pp + yy, B = 1.f - x2d;
            float den = fmaxf(1.f - 2.f * pp + x2d * yy, MINNORM);
            float num2 = fmaxf(A * A * x2d + B * B * yy - 2.f * A * B * pp, 0.f);
            float q = fminf(sqrtf(num2) / den, 1.0f - 1e-7f);
            float edd = (1.f + q) / (1.f - q);       // == exp(2*atanh(q))
            g_de[k + l] = edd;
            sum_d += edd;
        }
    }
    float inv_sd = 1.f / (wsum(sum_d) + 1e-16f);

    // ---- Pass B: hyperbolic softmax-weighted aggregation (masked x4) ----
    float sum_h = 0.f;
    float4 acc_h = make_float4(0.f, 0.f, 0.f, 0.f);
    for (int k = beg; k < end; k += 4) {
        int k1 = min(k + 1, end - 1), k2 = min(k + 2, end - 1), k3 = min(k + 3, end - 1);
        float m1 = (k + 1 < end) ? 1.f : 0.f;
        float m2 = (k + 2 < end) ? 1.f : 0.f;
        float m3 = (k + 3 < end) ? 1.f : 0.f;
        int s0 = g_csrc[k], s1 = g_csrc[k1], s2 = g_csrc[k2], s3 = g_csrc[k3];
        float4 l0 = ((const float4*)g_lx)[s0 * 32 + l];
        float4 l1 = ((const float4*)g_lx)[s1 * 32 + l];
        float4 l2 = ((const float4*)g_lx)[s2 * 32 + l];
        float4 l3 = ((const float4*)g_lx)[s3 * 32 + l];
        float d0 = g_de[k] * inv_sd,  d1 = g_de[k1] * inv_sd;
        float d2 = g_de[k2] * inv_sd, d3 = g_de[k3] * inv_sd;
        float a0 = __expf(lrelu((hi_l + g_hj[s0 * 4 + h]) * d0));
        float a1 = __expf(lrelu((hi_l + g_hj[s1 * 4 + h]) * d1)) * m1;
        float a2 = __expf(lrelu((hi_l + g_hj[s2 * 4 + h]) * d2)) * m2;
        float a3 = __expf(lrelu((hi_l + g_hj[s3 * 4 + h]) * d3)) * m3;
        acc_h.x = fmaf(a0, l0.x, fmaf(a1, l1.x, fmaf(a2, l2.x, fmaf(a3, l3.x, acc_h.x))));
        acc_h.y = fmaf(a0, l0.y, fmaf(a1, l1.y, fmaf(a2, l2.y, fmaf(a3, l3.y, acc_h.y))));
        acc_h.z = fmaf(a0, l0.z, fmaf(a1, l1.z, fmaf(a2, l2.z, fmaf(a3, l3.z, acc_h.z))));
        acc_h.w = fmaf(a0, l0.w, fmaf(a1, l1.w, fmaf(a2, l2.w, fmaf(a3, l3.w, acc_h.w))));
        if (leader) sum_h += a0 + a1 + a2 + a3;
    }

    float se = __shfl_sync(0xffffffffu, sum_e, h << 3);
    float sh = __shfl_sync(0xffffffffu, sum_h, h << 3);
    float inv_se = 1.f / (se + 1e-16f);
    float inv_sh = 1.f / (sh + 1e-16f);

    ((float4*)g_agg_e)[dn * 32 + l] = f4s(acc_e, inv_se);
    ((float4*)g_agg_h)[dn * 32 + l] = f4s(acc_h, inv_sh);
}

// ---------------- finalize kernel (warp per node; scalar-norm algebra) ----------------
__global__ __launch_bounds__(256) void finalize_kernel(const float* __restrict__ b_e,
                                                       const float* __restrict__ b_h,
                                                       const float* __restrict__ att_hf,
                                                       const float* __restrict__ att_ef,
                                                       float* __restrict__ out, int N) {
    int w = (blockIdx.x * blockDim.x + threadIdx.x) >> 5;
    int l = threadIdx.x & 31;
    if (w >= N) return;
    int n = w;
    float4 ae = ((const float4*)g_agg_e)[n * 32 + l];
    float4 ah = ((const float4*)g_agg_h)[n * 32 + l];
    float4 be = ((const float4*)b_e)[l];
    float4 eo = make_float4(fmaxf(ae.x + be.x, 0.f), fmaxf(ae.y + be.y, 0.f),
                            fmaxf(ae.z + be.z, 0.f), fmaxf(ae.w + be.w, 0.f));
    float4 bh = ((const float4*)b_h)[l];
    float4 ot = make_float4(fmaxf(ah.x + bh.x, 0.f), fmaxf(ah.y + bh.y, 0.f),
                            fmaxf(ah.z + bh.z, 0.f), fmaxf(ah.w + bh.w, 0.f));
    float nt = fmaxf(sqrtf(wsum(d4(ot, ot))), MINNORM);
    float nho = fminf(tanhf(nt), MAXN);
    float4 ho = f4s(ot, nho / nt);
    float x2 = nho * nho;
    float ne2 = wsum(d4(eo, eo));
    float ne = fmaxf(sqrtf(ne2), MINNORM);
    float nye = fminf(tanhf(ne), MAXN);
    float4 ye = f4s(eo, nye / ne);
    float y2 = nye * nye;
    float xy = wsum(d4(ho, ye));
    float A = 1.f - 2.f * xy + y2, B = 1.f - x2;
    float den = fmaxf(1.f - 2.f * xy + x2 * y2, MINNORM);
    float num2 = fmaxf(A * A * x2 + B * B * y2 - 2.f * A * B * xy, 0.f);
    float r = 2.f * atanhc(sqrtf(num2) / den) * att_hf[0];
    float ny = fmaxf(nye, MINNORM);
    float t3 = tanhf(r * atanhc(ny));
    float kxe = t3 / ny;
    float nxe2 = fabsf(kxe) * nye;
    float c2 = (nxe2 > MAXN) ? (MAXN / fmaxf(nxe2, MINNORM)) : 1.f;
    float kxe2 = kxe * c2;
    float4 xe2 = f4s(ye, kxe2);
    float nxe2c = nxe2 * c2;
    float y2b = nxe2c * nxe2c;
    float xyb = xy * kxe2;
    float A2 = 1.f + 2.f * xyb + y2b, B2 = 1.f - x2;
    float den2 = fmaxf(1.f + 2.f * xyb + x2 * y2b, MINNORM);
    float invden2 = 1.f / den2;
    float nhf2 = fmaxf(A2 * A2 * x2 + 2.f * A2 * B2 * xyb + B2 * B2 * y2b, 0.f)
                 * invden2 * invden2;
    float nhf = fmaxf(sqrtf(nhf2), MINNORM);
    float c3 = (nhf > MAXN) ? (MAXN / nhf) : 1.f;
    float4 hf = f4s(f4axby(A2, ho, B2, xe2), invden2 * c3);
    float nclh = fmaxf(nho, MINNORM);
    float alh = atanhc(nclh);
    float kl = alh / nclh;
    float4 lh = f4s(ho, kl);
    float dot_ho_eo = xy * ne / nye;
    float de = (alh * alh - 2.f * kl * dot_ho_eo + ne2) * att_ef[0];
    float4 ef = make_float4(eo.x + de * lh.x, eo.y + de * lh.y,
                            eo.z + de * lh.z, eo.w + de * lh.w);
    ((float4*)out)[n * 32 + l] = hf;
    ((float4*)out)[(size_t)N * 32 + n * 32 + l] = ef;
}

// ---------------- launch: node_e / node_h / CSR on three concurrent streams ----------------
extern "C" void kernel_launch(void* const* d_in, const int* in_sizes, int n_in,
                              void* d_out, int out_size) {
    const float* x_e      = (const float*)d_in[0];
    const float* x_h      = (const float*)d_in[1];
    const int*   ei       = (const int*)d_in[2];
    const float* W_e      = (const float*)d_in[3];
    const float* b_lin_e  = (const float*)d_in[4];
    const float* att_e    = (const float*)d_in[5];
    const float* b_e      = (const float*)d_in[6];
    const float* W_h      = (const float*)d_in[7];
    const float* b_lin_h  = (const float*)d_in[8];
    const float* att_h    = (const float*)d_in[9];
    const float* b_h      = (const float*)d_in[10];
    const float* att_hf   = (const float*)d_in[11];
    const float* att_ef   = (const float*)d_in[12];
    float* out = (float*)d_out;

    int N  = in_sizes[0] / D_;
    int E  = in_sizes[2] / 2;
    int EP = E + N;
    int nsb = (N + 255) / 256;
    int ninit = (N > 2 * D_ * D_) ? N : 2 * D_ * D_;

    static cudaStream_t s2 = nullptr, s3 = nullptr;
    static cudaEvent_t evFork = nullptr, evJoin2 = nullptr, evJoin3 = nullptr;
    if (s2 == nullptr) {
        cudaStreamCreateWithFlags(&s2, cudaStreamNonBlocking);
        cudaStreamCreateWithFlags(&s3, cudaStreamNonBlocking);
        cudaEventCreateWithFlags(&evFork, cudaEventDisableTiming);
        cudaEventCreateWithFlags(&evJoin2, cudaEventDisableTiming);
        cudaEventCreateWithFlags(&evJoin3, cudaEventDisableTiming);
    }

    // main stream: init (weights + deg zero)
    init_kernel<<<(ninit + 255) / 256, 256>>>(W_e, W_h, N);
    cudaEventRecord(evFork, 0);

    // side stream s2: CSR build chain
    cudaStreamWaitEvent(s2, evFork, 0);
    count_kernel<<<(EP + 255) / 256, 256, 0, s2>>>(ei, E, EP);
    scan1_kernel<<<nsb, 256, 0, s2>>>(N);
    scan2_kernel<<<1, 256, 0, s2>>>(nsb);
    scan3_kernel<<<(N + 255) / 256, 256, 0, s2>>>(N, EP);
    scatter_kernel<<<(EP + 255) / 256, 256, 0, s2>>>(ei, E, EP);
    cudaEventRecord(evJoin2, s2);

    // side stream s3: hyperbolic node kernel (concurrent with node_e)
    cudaStreamWaitEvent(s3, evFork, 0);
    node_h_kernel<<<(N + 31) / 32, 128, 0, s3>>>(x_h, b_lin_h, att_h, N);
    cudaEventRecord(evJoin3, s3);

    // main stream: euclidean node kernel
    node_e_kernel<<<(N + 31) / 32, 128>>>(x_e, b_lin_e, att_e, N);

    // join all, then edge aggregation, then finalize
    cudaStreamWaitEvent(0, evJoin2, 0);
    cudaStreamWaitEvent(0, evJoin3, 0);
    edge_kernel<<<(N * 32 + 255) / 256, 256>>>(N);
    finalize_kernel<<<(N * 32 + 255) / 256, 256>>>(b_e, b_h, att_hf, att_ef, out, N);
}

// round 14
// speedup vs baseline: 1.0082x; 1.0082x over previous
#include <cuda_runtime.h>
#include <math.h>

#define D_ 128
#define NMAX 50016
#define EPMAX 550032
#define MAXN 0.99999f
#define MINNORM 1e-15f

// ---------------- scratch ----------------
__device__ float  g_xe[NMAX * D_];
__device__ float  g_xh[NMAX * D_];
__device__ float  g_agg_e[NMAX * D_];
__device__ float  g_agg_h[NMAX * D_];
__device__ float  g_ai[NMAX * 4];
__device__ float  g_aj[NMAX * 4];
__device__ float  g_hi[NMAX * 4];
__device__ float  g_hj[NMAX * 4];
__device__ float2 g_nx2[NMAX];      // [ ||xh||^2 , logmap scale ]
__device__ float  g_de[EPMAX];      // exp(distance)
__device__ float  g_WtE[D_ * D_];
__device__ float  g_WtH[D_ * D_];
__device__ int    g_deg[NMAX];
__device__ int    g_cur[NMAX];
__device__ int    g_start[NMAX + 1];
__device__ int    g_csrc[EPMAX];
__device__ int    g_bsum[256];

// ---------------- helpers ----------------
__device__ __forceinline__ float atanhc(float x) {
    x = fminf(fmaxf(x, -1.0f + 1e-7f), 1.0f - 1e-7f);
    return atanhf(x);
}
__device__ __forceinline__ float wsum(float v) {
#pragma unroll
    for (int o = 16; o; o >>= 1) v += __shfl_xor_sync(0xffffffffu, v, o);
    return v;
}
__device__ __forceinline__ float d4(float4 a, float4 b) {
    return a.x * b.x + a.y * b.y + a.z * b.z + a.w * b.w;
}
__device__ __forceinline__ float4 f4s(float4 a, float s) {
    return make_float4(a.x * s, a.y * s, a.z * s, a.w * s);
}
__device__ __forceinline__ float4 f4axby(float a, float4 x, float b, float4 y) {
    return make_float4(a * x.x + b * y.x, a * x.y + b * y.y,
                       a * x.z + b * y.z, a * x.w + b * y.w);
}
__device__ __forceinline__ float lrelu(float v) { return v >= 0.f ? v : 0.2f * v; }

// packed f32x2 helpers (Blackwell FFMA2)
__device__ __forceinline__ void ffma2(unsigned long long &acc,
                                      unsigned long long a, unsigned long long b) {
    asm("fma.rn.f32x2 %0, %1, %2, %3;" : "=l"(acc) : "l"(a), "l"(b), "l"(acc));
}
__device__ __forceinline__ unsigned long long pack2(float s) {
    unsigned u = __float_as_uint(s);
    unsigned long long r;
    asm("mov.b64 %0, {%1, %1};" : "=l"(r) : "r"(u));
    return r;
}
__device__ __forceinline__ float4 unpack4(unsigned long long lo, unsigned long long hi) {
    float4 v;
    asm("mov.b64 {%0, %1}, %2;" : "=f"(v.x), "=f"(v.y) : "l"(lo));
    asm("mov.b64 {%0, %1}, %2;" : "=f"(v.z), "=f"(v.w) : "l"(hi));
    return v;
}

// ---------------- init: zero degrees + transpose weights ----------------
__global__ __launch_bounds__(256) void init_kernel(const float* __restrict__ We,
                                                   const float* __restrict__ Wh, int N) {
    int i = blockIdx.x * blockDim.x + threadIdx.x;
    if (i < N) g_deg[i] = 0;
    if (i < 2 * D_ * D_) {
        int m = i >> 14;
        int k = (i >> 7) & 127;
        int c = i & 127;
        if (m == 0) g_WtE[k * D_ + c] = We[c * D_ + k];
        else        g_WtH[k * D_ + c] = Wh[c * D_ + k];
    }
}

__global__ __launch_bounds__(256) void count_kernel(const int* __restrict__ ei, int E, int EP) {
    int e = blockIdx.x * blockDim.x + threadIdx.x;
    if (e >= EP) return;
    int dn = (e < E) ? ei[E + e] : (e - E);
    atomicAdd(&g_deg[dn], 1);
}

__global__ __launch_bounds__(256) void scan1_kernel(int N) {
    __shared__ int sm[256];
    int i = blockIdx.x * 256 + threadIdx.x;
    int v = (i < N) ? g_deg[i] : 0;
    sm[threadIdx.x] = v;
    __syncthreads();
#pragma unroll
    for (int d = 1; d < 256; d <<= 1) {
        int t = (threadIdx.x >= d) ? sm[threadIdx.x - d] : 0;
        __syncthreads();
        sm[threadIdx.x] += t;
        __syncthreads();
    }
    if (i < N) g_start[i] = sm[threadIdx.x] - v;
    if (threadIdx.x == 255) g_bsum[blockIdx.x] = sm[255];
}

__global__ __launch_bounds__(256) void scan2_kernel(int nb) {
    __shared__ int sm[256];
    int v = (threadIdx.x < nb) ? g_bsum[threadIdx.x] : 0;
    sm[threadIdx.x] = v;
    __syncthreads();
#pragma unroll
    for (int d = 1; d < 256; d <<= 1) {
        int t = (threadIdx.x >= d) ? sm[threadIdx.x - d] : 0;
        __syncthreads();
        sm[threadIdx.x] += t;
        __syncthreads();
    }
    g_bsum[threadIdx.x] = sm[threadIdx.x] - v;
}

__global__ __launch_bounds__(256) void scan3_kernel(int N, int EP) {
    int i = blockIdx.x * 256 + threadIdx.x;
    if (i < N) { g_start[i] += g_bsum[i >> 8]; g_cur[i] = 0; }
    if (i == 0) g_start[N] = EP;
}

__global__ __launch_bounds__(256) void scatter_kernel(const int* __restrict__ ei, int E, int EP) {
    int e = blockIdx.x * blockDim.x + threadIdx.x;
    if (e >= EP) return;
    int s, dn;
    if (e < E) { s = ei[e]; dn = ei[E + e]; } else { s = dn = e - E; }
    int pos = atomicAdd(&g_cur[dn], 1);
    g_csrc[g_start[dn] + pos] = s;
}

// ---------------- node kernels: 8 nodes/warp ----------------
__global__ __launch_bounds__(128) void node_e_kernel(const float* __restrict__ x,
                                                     const float* __restrict__ b_lin,
                                                     const float* __restrict__ att,
                                                     int N) {
    __shared__ float sx[4][8][D_];
    int w = threadIdx.x >> 5, l = threadIdx.x & 31;
    int base = blockIdx.x * 32 + w * 8;
    if (base >= N) return;
#pragma unroll
    for (int j = 0; j < 8; j++) {
        int n = min(base + j, N - 1);
        ((float4*)sx[w][j])[l] = ((const float4*)x)[n * 32 + l];
    }
    __syncwarp();
    unsigned long long acc[8][2];
#pragma unroll
    for (int j = 0; j < 8; j++) { acc[j][0] = 0ull; acc[j][1] = 0ull; }
    const ulonglong2* Wt = (const ulonglong2*)g_WtE;
#pragma unroll 2
    for (int k = 0; k < D_; k++) {
        ulonglong2 wv = Wt[k * 32 + l];
#pragma unroll
        for (int j = 0; j < 8; j++) {
            unsigned long long ss = pack2(sx[w][j][k]);
            ffma2(acc[j][0], ss, wv.x);
            ffma2(acc[j][1], ss, wv.y);
        }
    }
    float4 bv = ((const float4*)b_lin)[l];
    int h = l >> 3, j0 = (l & 7) * 4;
    const float* at  = att + h * 64 + j0;
    const float* at2 = at + 32;
#pragma unroll
    for (int j = 0; j < 8; j++) {
        int n = base + j;
        if (n >= N) break;
        float4 a = unpack4(acc[j][0], acc[j][1]);
        a.x += bv.x; a.y += bv.y; a.z += bv.z; a.w += bv.w;
        ((float4*)g_xe)[n * 32 + l] = a;
        float pi = a.x * at[0]  + a.y * at[1]  + a.z * at[2]  + a.w * at[3];
        float pj = a.x * at2[0] + a.y * at2[1] + a.z * at2[2] + a.w * at2[3];
#pragma unroll
        for (int o = 4; o; o >>= 1) {
            pi += __shfl_down_sync(0xffffffffu, pi, o, 8);
            pj += __shfl_down_sync(0xffffffffu, pj, o, 8);
        }
        if ((l & 7) == 0) { g_ai[n * 4 + h] = pi; g_aj[n * 4 + h] = pj; }
    }
}

__global__ __launch_bounds__(128) void node_h_kernel(const float* __restrict__ x,
                                                     const float* __restrict__ b_lin,
                                                     const float* __restrict__ att,
                                                     int N) {
    __shared__ float sx[4][8][D_];
    int w = threadIdx.x >> 5, l = threadIdx.x & 31;
    int base = blockIdx.x * 32 + w * 8;
    if (base >= N) return;
    float pnx[8];
#pragma unroll
    for (int j = 0; j < 8; j++) {
        int n = min(base + j, N - 1);
        float4 xv = ((const float4*)x)[n * 32 + l];
        ((float4*)sx[w][j])[l] = xv;
        pnx[j] = d4(xv, xv);
    }
#pragma unroll
    for (int o = 16; o; o >>= 1) {
#pragma unroll
        for (int j = 0; j < 8; j++) pnx[j] += __shfl_xor_sync(0xffffffffu, pnx[j], o);
    }
    __syncwarp();
    unsigned long long acc[8][2];
#pragma unroll
    for (int j = 0; j < 8; j++) { acc[j][0] = 0ull; acc[j][1] = 0ull; }
    const ulonglong2* Wt = (const ulonglong2*)g_WtH;
#pragma unroll 2
    for (int k = 0; k < D_; k++) {
        ulonglong2 wv = Wt[k * 32 + l];
#pragma unroll
        for (int j = 0; j < 8; j++) {
            unsigned long long ss = pack2(sx[w][j][k]);
            ffma2(acc[j][0], ss, wv.x);
            ffma2(acc[j][1], ss, wv.y);
        }
    }
    float4 bvv = ((const float4*)b_lin)[l];
    float nb = fmaxf(sqrtf(wsum(d4(bvv, bvv))), MINNORM);
    float nhb = fminf(tanhf(nb), MAXN);
    float4 hb = f4s(bvv, nhb / nb);
    float y2 = nhb * nhb;

    float4 mx[8];
    float pm[8];
#pragma unroll
    for (int j = 0; j < 8; j++) {
        mx[j] = unpack4(acc[j][0], acc[j][1]);
        pm[j] = d4(mx[j], mx[j]);
    }
#pragma unroll
    for (int o = 16; o; o >>= 1) {
#pragma unroll
        for (int j = 0; j < 8; j++) pm[j] += __shfl_xor_sync(0xffffffffu, pm[j], o);
    }
    float nmv[8];
#pragma unroll
    for (int j = 0; j < 8; j++) {
        float n_x = fmaxf(sqrtf(pnx[j]), MINNORM);
        float n_mx = fmaxf(sqrtf(pm[j]), MINNORM);
        nmv[j] = fminf(tanhf(n_mx / n_x * atanhc(n_x)), MAXN);
        float s = nmv[j] / n_mx;
        mx[j] = f4s(mx[j], s);
    }
    float pxy[8];
#pragma unroll
    for (int j = 0; j < 8; j++) pxy[j] = d4(mx[j], hb);
#pragma unroll
    for (int o = 16; o; o >>= 1) {
#pragma unroll
        for (int j = 0; j < 8; j++) pxy[j] += __shfl_xor_sync(0xffffffffu, pxy[j], o);
    }

    int h = l >> 3, j0 = (l & 7) * 4;
    const float* at  = att + h * 64 + j0;
    const float* at2 = at + 32;
#pragma unroll
    for (int j = 0; j < 8; j++) {
        int n = base + j;
        if (n >= N) break;
        float x2 = nmv[j] * nmv[j];
        float xy = pxy[j];
        float A = 1.f + 2.f * xy + y2, B = 1.f - x2;
        float den = fmaxf(1.f + 2.f * xy + x2 * y2, MINNORM);
        float invden = 1.f / den;
        float nxh2 = fmaxf(A * A * x2 + 2.f * A * B * xy + B * B * y2, 0.f)
                     * invden * invden;
        float nxh = fmaxf(sqrtf(nxh2), MINNORM);
        float c = (nxh > MAXN) ? (MAXN / nxh) : 1.f;
        float4 xh = f4s(f4axby(A, mx[j], B, hb), invden * c);
        float nfin = c * nxh;
        float x2f = nfin * nfin;
        ((float4*)g_xh)[n * 32 + l] = xh;
        float ncl = fmaxf(nfin, MINNORM);
        float lsc = atanhc(ncl) / ncl;               // logmap scale (per node)
        if (l == 0) g_nx2[n] = make_float2(x2f, lsc);
        float4 lx = f4s(xh, lsc);
        float pi = lx.x * at[0]  + lx.y * at[1]  + lx.z * at[2]  + lx.w * at[3];
        float pj = lx.x * at2[0] + lx.y * at2[1] + lx.z * at2[2] + lx.w * at2[3];
#pragma unroll
        for (int o = 4; o; o >>= 1) {
            pi += __shfl_down_sync(0xffffffffu, pi, o, 8);
            pj += __shfl_down_sync(0xffffffffu, pj, o, 8);
        }
        if ((l & 7) == 0) { g_hi[n * 4 + h] = pi; g_hj[n * 4 + h] = pj; }
    }
}

// ---------------- edge kernel (8-edge masked batches; stores normalized aggregates) ----------------
__global__ __launch_bounds__(256) void edge_kernel(int N) {
    int w = (blockIdx.x * blockDim.x + threadIdx.x) >> 5;
    int l = threadIdx.x & 31;
    if (w >= N) return;
    int dn = w;
    int beg = g_start[dn], end = g_start[dn + 1];
    int h = l >> 3;
    bool leader = (l & 7) == 0;

    float4 xd  = ((const float4*)g_xh)[dn * 32 + l];
    float  x2d = g_nx2[dn].x;
    float  ai_l = g_ai[dn * 4 + h];
    float  hi_l = g_hi[dn * 4 + h];

    // ---- Pass A: distances + euclid softmax-weighted aggregation (masked x8) ----
    float sum_d = 0.f, sum_e = 0.f;
    float4 acc_e = make_float4(0.f, 0.f, 0.f, 0.f);
    for (int k = beg; k < end; k += 8) {
        int e1 = min(k + 1, end - 1), e2 = min(k + 2, end - 1), e3 = min(k + 3, end - 1);
        int e4 = min(k + 4, end - 1), e5 = min(k + 5, end - 1), e6 = min(k + 6, end - 1);
        int e7 = min(k + 7, end - 1);
        float m1 = (k + 1 < end) ? 1.f : 0.f, m2 = (k + 2 < end) ? 1.f : 0.f;
        float m3 = (k + 3 < end) ? 1.f : 0.f, m4 = (k + 4 < end) ? 1.f : 0.f;
        float m5 = (k + 5 < end) ? 1.f : 0.f, m6 = (k + 6 < end) ? 1.f : 0.f;
        float m7 = (k + 7 < end) ? 1.f : 0.f;
        int s0 = g_csrc[k],  s1 = g_csrc[e1], s2 = g_csrc[e2], s3 = g_csrc[e3];
        int s4 = g_csrc[e4], s5 = g_csrc[e5], s6 = g_csrc[e6], s7 = g_csrc[e7];
        // euclid weights + aggregation
        float w0 = __expf(lrelu(ai_l + g_aj[s0 * 4 + h]));
        float w1 = __expf(lrelu(ai_l + g_aj[s1 * 4 + h])) * m1;
        float w2 = __expf(lrelu(ai_l + g_aj[s2 * 4 + h])) * m2;
        float w3 = __expf(lrelu(ai_l + g_aj[s3 * 4 + h])) * m3;
        float w4 = __expf(lrelu(ai_l + g_aj[s4 * 4 + h])) * m4;
        float w5 = __expf(lrelu(ai_l + g_aj[s5 * 4 + h])) * m5;
        float w6 = __expf(lrelu(ai_l + g_aj[s6 * 4 + h])) * m6;
        float w7 = __expf(lrelu(ai_l + g_aj[s7 * 4 + h])) * m7;
        {
            float4 q0 = ((const float4*)g_xe)[s0 * 32 + l];
            float4 q1 = ((const float4*)g_xe)[s1 * 32 + l];
            float4 q2 = ((const float4*)g_xe)[s2 * 32 + l];
            float4 q3 = ((const float4*)g_xe)[s3 * 32 + l];
            float4 q4 = ((const float4*)g_xe)[s4 * 32 + l];
            float4 q5 = ((const float4*)g_xe)[s5 * 32 + l];
            float4 q6 = ((const float4*)g_xe)[s6 * 32 + l];
            float4 q7 = ((const float4*)g_xe)[s7 * 32 + l];
            acc_e.x += w0*q0.x + w1*q1.x + w2*q2.x + w3*q3.x + w4*q4.x + w5*q5.x + w6*q6.x + w7*q7.x;
            acc_e.y += w0*q0.y + w1*q1.y + w2*q2.y + w3*q3.y + w4*q4.y + w5*q5.y + w6*q6.y + w7*q7.y;
            acc_e.z += w0*q0.z + w1*q1.z + w2*q2.z + w3*q3.z + w4*q4.z + w5*q5.z + w6*q6.z + w7*q7.z;
            acc_e.w += w0*q0.w + w1*q1.w + w2*q2.w + w3*q3.w + w4*q4.w + w5*q5.w + w6*q6.w + w7*q7.w;
        }
        if (leader) sum_e += (w0 + w1 + w2 + w3) + (w4 + w5 + w6 + w7);
        // hyperbolic dots (8 interleaved trees)
        float p0, p1, p2, p3, p4, p5, p6, p7;
        {
            float4 v0 = ((const float4*)g_xh)[s0 * 32 + l];
            float4 v1 = ((const float4*)g_xh)[s1 * 32 + l];
            float4 v2 = ((const float4*)g_xh)[s2 * 32 + l];
            float4 v3 = ((const float4*)g_xh)[s3 * 32 + l];
            float4 v4 = ((const float4*)g_xh)[s4 * 32 + l];
            float4 v5 = ((const float4*)g_xh)[s5 * 32 + l];
            float4 v6 = ((const float4*)g_xh)[s6 * 32 + l];
            float4 v7 = ((const float4*)g_xh)[s7 * 32 + l];
            p0 = d4(xd, v0); p1 = d4(xd, v1); p2 = d4(xd, v2); p3 = d4(xd, v3);
            p4 = d4(xd, v4); p5 = d4(xd, v5); p6 = d4(xd, v6); p7 = d4(xd, v7);
        }
#pragma unroll
        for (int o = 16; o; o >>= 1) {
            p0 += __shfl_xor_sync(0xffffffffu, p0, o);
            p1 += __shfl_xor_sync(0xffffffffu, p1, o);
            p2 += __shfl_xor_sync(0xffffffffu, p2, o);
            p3 += __shfl_xor_sync(0xffffffffu, p3, o);
            p4 += __shfl_xor_sync(0xffffffffu, p4, o);
            p5 += __shfl_xor_sync(0xffffffffu, p5, o);
            p6 += __shfl_xor_sync(0xffffffffu, p6, o);
            p7 += __shfl_xor_sync(0xffffffffu, p7, o);
        }
        if (l < 8 && k + l < end) {
            float pp = (l & 4) ? ((l & 2) ? ((l & 1) ? p7 : p6) : ((l & 1) ? p5 : p4))
                               : ((l & 2) ? ((l & 1) ? p3 : p2) : ((l & 1) ? p1 : p0));
            int ssel  = (l & 4) ? ((l & 2) ? ((l & 1) ? s7 : s6) : ((l & 1) ? s5 : s4))
                                : ((l & 2) ? ((l & 1) ? s3 : s2) : ((l & 1) ? s1 : s0));
            float yy = g_nx2[ssel].x;
            float A = 1.f - 2.f * pp + yy, B = 1.f - x2d;
            float den = fmaxf(1.f - 2.f * pp + x2d * yy, MINNORM);
            float num2 = fmaxf(A * A * x2d + B * B * yy - 2.f * A * B * pp, 0.f);
            float q = fminf(sqrtf(num2) / den, 1.0f - 1e-7f);
            float edd = (1.f + q) / (1.f - q);       // == exp(2*atanh(q))
            g_de[k + l] = edd;
            sum_d += edd;
        }
    }
    float inv_sd = 1.f / (wsum(sum_d) + 1e-16f);

    // ---- Pass B: hyperbolic softmax-weighted aggregation (masked x8, lx = lsc*xh) ----
    float sum_h = 0.f;
    float4 acc_h = make_float4(0.f, 0.f, 0.f, 0.f);
    for (int k = beg; k < end; k += 8) {
        int e1 = min(k + 1, end - 1), e2 = min(k + 2, end - 1), e3 = min(k + 3, end - 1);
        int e4 = min(k + 4, end - 1), e5 = min(k + 5, end - 1), e6 = min(k + 6, end - 1);
        int e7 = min(k + 7, end - 1);
        float m1 = (k + 1 < end) ? 1.f : 0.f, m2 = (k + 2 < end) ? 1.f : 0.f;
        float m3 = (k + 3 < end) ? 1.f : 0.f, m4 = (k + 4 < end) ? 1.f : 0.f;
        float m5 = (k + 5 < end) ? 1.f : 0.f, m6 = (k + 6 < end) ? 1.f : 0.f;
        float m7 = (k + 7 < end) ? 1.f : 0.f;
        int s0 = g_csrc[k],  s1 = g_csrc[e1], s2 = g_csrc[e2], s3 = g_csrc[e3];
        int s4 = g_csrc[e4], s5 = g_csrc[e5], s6 = g_csrc[e6], s7 = g_csrc[e7];
        float d0 = g_de[k]  * inv_sd, d1 = g_de[e1] * inv_sd;
        float d2 = g_de[e2] * inv_sd, d3 = g_de[e3] * inv_sd;
        float d4v = g_de[e4] * inv_sd, d5 = g_de[e5] * inv_sd;
        float d6 = g_de[e6] * inv_sd, d7 = g_de[e7] * inv_sd;
        float a0 = __expf(lrelu((hi_l + g_hj[s0 * 4 + h]) * d0));
        float a1 = __expf(lrelu((hi_l + g_hj[s1 * 4 + h]) * d1)) * m1;
        float a2 = __expf(lrelu((hi_l + g_hj[s2 * 4 + h]) * d2)) * m2;
        float a3 = __expf(lrelu((hi_l + g_hj[s3 * 4 + h]) * d3)) * m3;
        float a4 = __expf(lrelu((hi_l + g_hj[s4 * 4 + h]) * d4v)) * m4;
        float a5 = __expf(lrelu((hi_l + g_hj[s5 * 4 + h]) * d5)) * m5;
        float a6 = __expf(lrelu((hi_l + g_hj[s6 * 4 + h]) * d6)) * m6;
        float a7 = __expf(lrelu((hi_l + g_hj[s7 * 4 + h]) * d7)) * m7;
        if (leader) sum_h += (a0 + a1 + a2 + a3) + (a4 + a5 + a6 + a7);
        // fold per-source logmap scale into the weight
        float b0 = a0 * g_nx2[s0].y, b1 = a1 * g_nx2[s1].y;
        float b2 = a2 * g_nx2[s2].y, b3 = a3 * g_nx2[s3].y;
        float b4 = a4 * g_nx2[s4].y, b5 = a5 * g_nx2[s5].y;
        float b6 = a6 * g_nx2[s6].y, b7 = a7 * g_nx2[s7].y;
        float4 v0 = ((const float4*)g_xh)[s0 * 32 + l];
        float4 v1 = ((const float4*)g_xh)[s1 * 32 + l];
        float4 v2 = ((const float4*)g_xh)[s2 * 32 + l];
        float4 v3 = ((const float4*)g_xh)[s3 * 32 + l];
        float4 v4 = ((const float4*)g_xh)[s4 * 32 + l];
        float4 v5 = ((const float4*)g_xh)[s5 * 32 + l];
        float4 v6 = ((const float4*)g_xh)[s6 * 32 + l];
        float4 v7 = ((const float4*)g_xh)[s7 * 32 + l];
        acc_h.x += b0*v0.x + b1*v1.x + b2*v2.x + b3*v3.x + b4*v4.x + b5*v5.x + b6*v6.x + b7*v7.x;
        acc_h.y += b0*v0.y + b1*v1.y + b2*v2.y + b3*v3.y + b4*v4.y + b5*v5.y + b6*v6.y + b7*v7.y;
        acc_h.z += b0*v0.z + b1*v1.z + b2*v2.z + b3*v3.z + b4*v4.z + b5*v5.z + b6*v6.z + b7*v7.z;
        acc_h.w += b0*v0.w + b1*v1.w + b2*v2.w + b3*v3.w + b4*v4.w + b5*v5.w + b6*v6.w + b7*v7.w;
    }

    float se = __shfl_sync(0xffffffffu, sum_e, h << 3);
    float sh = __shfl_sync(0xffffffffu, sum_h, h << 3);
    float inv_se = 1.f / (se + 1e-16f);
    float inv_sh = 1.f / (sh + 1e-16f);

    ((float4*)g_agg_e)[dn * 32 + l] = f4s(acc_e, inv_se);
    ((float4*)g_agg_h)[dn * 32 + l] = f4s(acc_h, inv_sh);
}

// ---------------- finalize kernel (warp per node; scalar-norm algebra) ----------------
__global__ __launch_bounds__(256) void finalize_kernel(const float* __restrict__ b_e,
                                                       const float* __restrict__ b_h,
                                                       const float* __restrict__ att_hf,
                                                       const float* __restrict__ att_ef,
                                                       float* __restrict__ out, int N) {
    int w = (blockIdx.x * blockDim.x + threadIdx.x) >> 5;
    int l = threadIdx.x & 31;
    if (w >= N) return;
    int n = w;
    float4 ae = ((const float4*)g_agg_e)[n * 32 + l];
    float4 ah = ((const float4*)g_agg_h)[n * 32 + l];
    float4 be = ((const float4*)b_e)[l];
    float4 eo = make_float4(fmaxf(ae.x + be.x, 0.f), fmaxf(ae.y + be.y, 0.f),
                            fmaxf(ae.z + be.z, 0.f), fmaxf(ae.w + be.w, 0.f));
    float4 bh = ((const float4*)b_h)[l];
    float4 ot = make_float4(fmaxf(ah.x + bh.x, 0.f), fmaxf(ah.y + bh.y, 0.f),
                            fmaxf(ah.z + bh.z, 0.f), fmaxf(ah.w + bh.w, 0.f));
    float nt = fmaxf(sqrtf(wsum(d4(ot, ot))), MINNORM);
    float nho = fminf(tanhf(nt), MAXN);
    float4 ho = f4s(ot, nho / nt);
    float x2 = nho * nho;
    float ne2 = wsum(d4(eo, eo));
    float ne = fmaxf(sqrtf(ne2), MINNORM);
    float nye = fminf(tanhf(ne), MAXN);
    float4 ye = f4s(eo, nye / ne);
    float y2 = nye * nye;
    float xy = wsum(d4(ho, ye));
    float A = 1.f - 2.f * xy + y2, B = 1.f - x2;
    float den = fmaxf(1.f - 2.f * xy + x2 * y2, MINNORM);
    float num2 = fmaxf(A * A * x2 + B * B * y2 - 2.f * A * B * xy, 0.f);
    float r = 2.f * atanhc(sqrtf(num2) / den) * att_hf[0];
    float ny = fmaxf(nye, MINNORM);
    float t3 = tanhf(r * atanhc(ny));
    float kxe = t3 / ny;
    float nxe2 = fabsf(kxe) * nye;
    float c2 = (nxe2 > MAXN) ? (MAXN / fmaxf(nxe2, MINNORM)) : 1.f;
    float kxe2 = kxe * c2;
    float4 xe2 = f4s(ye, kxe2);
    float nxe2c = nxe2 * c2;
    float y2b = nxe2c * nxe2c;
    float xyb = xy * kxe2;
    float A2 = 1.f + 2.f * xyb + y2b, B2 = 1.f - x2;
    float den2 = fmaxf(1.f + 2.f * xyb + x2 * y2b, MINNORM);
    float invden2 = 1.f / den2;
    float nhf2 = fmaxf(A2 * A2 * x2 + 2.f * A2 * B2 * xyb + B2 * B2 * y2b, 0.f)
                 * invden2 * invden2;
    float nhf = fmaxf(sqrtf(nhf2), MINNORM);
    float c3 = (nhf > MAXN) ? (MAXN / nhf) : 1.f;
    float4 hf = f4s(f4axby(A2, ho, B2, xe2), invden2 * c3);
    float nclh = fmaxf(nho, MINNORM);
    float alh = atanhc(nclh);
    float kl = alh / nclh;
    float4 lh = f4s(ho, kl);
    float dot_ho_eo = xy * ne / nye;
    float de = (alh * alh - 2.f * kl * dot_ho_eo + ne2) * att_ef[0];
    float4 ef = make_float4(eo.x + de * lh.x, eo.y + de * lh.y,
                            eo.z + de * lh.z, eo.w + de * lh.w);
    ((float4*)out)[n * 32 + l] = hf;
    ((float4*)out)[(size_t)N * 32 + n * 32 + l] = ef;
}

// ---------------- launch: node_e / node_h / CSR on three concurrent streams ----------------
extern "C" void kernel_launch(void* const* d_in, const int* in_sizes, int n_in,
                              void* d_out, int out_size) {
    const float* x_e      = (const float*)d_in[0];
    const float* x_h      = (const float*)d_in[1];
    const int*   ei       = (const int*)d_in[2];
    const float* W_e      = (const float*)d_in[3];
    const float* b_lin_e  = (const float*)d_in[4];
    const float* att_e    = (const float*)d_in[5];
    const float* b_e      = (const float*)d_in[6];
    const float* W_h      = (const float*)d_in[7];
    const float* b_lin_h  = (const float*)d_in[8];
    const float* att_h    = (const float*)d_in[9];
    const float* b_h      = (const float*)d_in[10];
    const float* att_hf   = (const float*)d_in[11];
    const float* att_ef   = (const float*)d_in[12];
    float* out = (float*)d_out;

    int N  = in_sizes[0] / D_;
    int E  = in_sizes[2] / 2;
    int EP = E + N;
    int nsb = (N + 255) / 256;
    int ninit = (N > 2 * D_ * D_) ? N : 2 * D_ * D_;

    static cudaStream_t s2 = nullptr, s3 = nullptr;
    static cudaEvent_t evFork = nullptr, evJoin2 = nullptr, evJoin3 = nullptr;
    if (s2 == nullptr) {
        cudaStreamCreateWithFlags(&s2, cudaStreamNonBlocking);
        cudaStreamCreateWithFlags(&s3, cudaStreamNonBlocking);
        cudaEventCreateWithFlags(&evFork, cudaEventDisableTiming);
        cudaEventCreateWithFlags(&evJoin2, cudaEventDisableTiming);
        cudaEventCreateWithFlags(&evJoin3, cudaEventDisableTiming);
    }

    // main stream: init (weights + deg zero)
    init_kernel<<<(ninit + 255) / 256, 256>>>(W_e, W_h, N);
    cudaEventRecord(evFork, 0);

    // side stream s2: CSR build chain
    cudaStreamWaitEvent(s2, evFork, 0);
    count_kernel<<<(EP + 255) / 256, 256, 0, s2>>>(ei, E, EP);
    scan1_kernel<<<nsb, 256, 0, s2>>>(N);
    scan2_kernel<<<1, 256, 0, s2>>>(nsb);
    scan3_kernel<<<(N + 255) / 256, 256, 0, s2>>>(N, EP);
    scatter_kernel<<<(EP + 255) / 256, 256, 0, s2>>>(ei, E, EP);
    cudaEventRecord(evJoin2, s2);

    // side stream s3: hyperbolic node kernel (concurrent with node_e)
    cudaStreamWaitEvent(s3, evFork, 0);
    node_h_kernel<<<(N + 31) / 32, 128, 0, s3>>>(x_h, b_lin_h, att_h, N);
    cudaEventRecord(evJoin3, s3);

    // main stream: euclidean node kernel
    node_e_kernel<<<(N + 31) / 32, 128>>>(x_e, b_lin_e, att_e, N);

    // join all, then edge aggregation, then finalize
    cudaStreamWaitEvent(0, evJoin2, 0);
    cudaStreamWaitEvent(0, evJoin3, 0);
    edge_kernel<<<(N * 32 + 255) / 256, 256>>>(N);
    finalize_kernel<<<(N * 32 + 255) / 256, 256>>>(b_e, b_h, att_hf, att_ef, out, N);
}

// round 16
// speedup vs baseline: 1.0903x; 1.0815x over previous
#include <cuda_runtime.h>
#include <cuda_fp16.h>
#include <math.h>

#define D_ 128
#define NMAX 50016
#define EPMAX 550032
#define MAXN 0.99999f
#define MINNORM 1e-15f

// ---------------- scratch ----------------
__device__ float  g_xh[NMAX * D_];
__device__ __half g_xe16[NMAX * D_];
__device__ __half g_lx16[NMAX * D_];
__device__ float  g_agg_e[NMAX * D_];
__device__ float  g_agg_h[NMAX * D_];
__device__ float  g_ai[NMAX * 4];
__device__ float  g_aj[NMAX * 4];
__device__ float  g_hi[NMAX * 4];
__device__ float  g_hj[NMAX * 4];
__device__ float  g_x2[NMAX];
__device__ float  g_de[EPMAX];      // exp(distance)
__device__ float  g_WtE[D_ * D_];
__device__ float  g_WtH[D_ * D_];
__device__ int    g_deg[NMAX];
__device__ int    g_cur[NMAX];
__device__ int    g_start[NMAX + 1];
__device__ int    g_csrc[EPMAX];
__device__ int    g_bsum[256];

// ---------------- helpers ----------------
__device__ __forceinline__ float atanhc(float x) {
    x = fminf(fmaxf(x, -1.0f + 1e-7f), 1.0f - 1e-7f);
    return atanhf(x);
}
__device__ __forceinline__ float wsum(float v) {
#pragma unroll
    for (int o = 16; o; o >>= 1) v += __shfl_xor_sync(0xffffffffu, v, o);
    return v;
}
__device__ __forceinline__ float d4(float4 a, float4 b) {
    return a.x * b.x + a.y * b.y + a.z * b.z + a.w * b.w;
}
__device__ __forceinline__ float4 f4s(float4 a, float s) {
    return make_float4(a.x * s, a.y * s, a.z * s, a.w * s);
}
__device__ __forceinline__ float4 f4axby(float a, float4 x, float b, float4 y) {
    return make_float4(a * x.x + b * y.x, a * x.y + b * y.y,
                       a * x.z + b * y.z, a * x.w + b * y.w);
}
__device__ __forceinline__ float lrelu(float v) { return v >= 0.f ? v : 0.2f * v; }

// pack float4 -> 4x fp16 in uint2
__device__ __forceinline__ uint2 pack_h4(float4 v) {
    __half2 h01 = __floats2half2_rn(v.x, v.y);
    __half2 h23 = __floats2half2_rn(v.z, v.w);
    uint2 u;
    u.x = *reinterpret_cast<unsigned*>(&h01);
    u.y = *reinterpret_cast<unsigned*>(&h23);
    return u;
}
// unpack uint2 (4x fp16) -> float4
__device__ __forceinline__ float4 unpack_h4(uint2 u) {
    __half2 h01 = *reinterpret_cast<__half2*>(&u.x);
    __half2 h23 = *reinterpret_cast<__half2*>(&u.y);
    float2 f01 = __half22float2(h01);
    float2 f23 = __half22float2(h23);
    return make_float4(f01.x, f01.y, f23.x, f23.y);
}

// packed f32x2 helpers (Blackwell FFMA2)
__device__ __forceinline__ void ffma2(unsigned long long &acc,
                                      unsigned long long a, unsigned long long b) {
    asm("fma.rn.f32x2 %0, %1, %2, %3;" : "=l"(acc) : "l"(a), "l"(b), "l"(acc));
}
__device__ __forceinline__ unsigned long long pack2(float s) {
    unsigned u = __float_as_uint(s);
    unsigned long long r;
    asm("mov.b64 %0, {%1, %1};" : "=l"(r) : "r"(u));
    return r;
}
__device__ __forceinline__ float4 unpack4(unsigned long long lo, unsigned long long hi) {
    float4 v;
    asm("mov.b64 {%0, %1}, %2;" : "=f"(v.x), "=f"(v.y) : "l"(lo));
    asm("mov.b64 {%0, %1}, %2;" : "=f"(v.z), "=f"(v.w) : "l"(hi));
    return v;
}

// ---------------- init: zero degrees + transpose weights ----------------
__global__ __launch_bounds__(256) void init_kernel(const float* __restrict__ We,
                                                   const float* __restrict__ Wh, int N) {
    int i = blockIdx.x * blockDim.x + threadIdx.x;
    if (i < N) g_deg[i] = 0;
    if (i < 2 * D_ * D_) {
        int m = i >> 14;
        int k = (i >> 7) & 127;
        int c = i & 127;
        if (m == 0) g_WtE[k * D_ + c] = We[c * D_ + k];
        else        g_WtH[k * D_ + c] = Wh[c * D_ + k];
    }
}

__global__ __launch_bounds__(256) void count_kernel(const int* __restrict__ ei, int E, int EP) {
    int e = blockIdx.x * blockDim.x + threadIdx.x;
    if (e >= EP) return;
    int dn = (e < E) ? ei[E + e] : (e - E);
    atomicAdd(&g_deg[dn], 1);
}

__global__ __launch_bounds__(256) void scan1_kernel(int N) {
    __shared__ int sm[256];
    int i = blockIdx.x * 256 + threadIdx.x;
    int v = (i < N) ? g_deg[i] : 0;
    sm[threadIdx.x] = v;
    __syncthreads();
#pragma unroll
    for (int d = 1; d < 256; d <<= 1) {
        int t = (threadIdx.x >= d) ? sm[threadIdx.x - d] : 0;
        __syncthreads();
        sm[threadIdx.x] += t;
        __syncthreads();
    }
    if (i < N) g_start[i] = sm[threadIdx.x] - v;
    if (threadIdx.x == 255) g_bsum[blockIdx.x] = sm[255];
}

__global__ __launch_bounds__(256) void scan2_kernel(int nb) {
    __shared__ int sm[256];
    int v = (threadIdx.x < nb) ? g_bsum[threadIdx.x] : 0;
    sm[threadIdx.x] = v;
    __syncthreads();
#pragma unroll
    for (int d = 1; d < 256; d <<= 1) {
        int t = (threadIdx.x >= d) ? sm[threadIdx.x - d] : 0;
        __syncthreads();
        sm[threadIdx.x] += t;
        __syncthreads();
    }
    g_bsum[threadIdx.x] = sm[threadIdx.x] - v;
}

__global__ __launch_bounds__(256) void scan3_kernel(int N, int EP) {
    int i = blockIdx.x * 256 + threadIdx.x;
    if (i < N) { g_start[i] += g_bsum[i >> 8]; g_cur[i] = 0; }
    if (i == 0) g_start[N] = EP;
}

__global__ __launch_bounds__(256) void scatter_kernel(const int* __restrict__ ei, int E, int EP) {
    int e = blockIdx.x * blockDim.x + threadIdx.x;
    if (e >= EP) return;
    int s, dn;
    if (e < E) { s = ei[e]; dn = ei[E + e]; } else { s = dn = e - E; }
    int pos = atomicAdd(&g_cur[dn], 1);
    g_csrc[g_start[dn] + pos] = s;
}

// ---------------- node kernels: 8 nodes/warp ----------------
__global__ __launch_bounds__(128) void node_e_kernel(const float* __restrict__ x,
                                                     const float* __restrict__ b_lin,
                                                     const float* __restrict__ att,
                                                     int N) {
    __shared__ float sx[4][8][D_];
    int w = threadIdx.x >> 5, l = threadIdx.x & 31;
    int base = blockIdx.x * 32 + w * 8;
    if (base >= N) return;
#pragma unroll
    for (int j = 0; j < 8; j++) {
        int n = min(base + j, N - 1);
        ((float4*)sx[w][j])[l] = ((const float4*)x)[n * 32 + l];
    }
    __syncwarp();
    unsigned long long acc[8][2];
#pragma unroll
    for (int j = 0; j < 8; j++) { acc[j][0] = 0ull; acc[j][1] = 0ull; }
    const ulonglong2* Wt = (const ulonglong2*)g_WtE;
#pragma unroll 2
    for (int k = 0; k < D_; k++) {
        ulonglong2 wv = Wt[k * 32 + l];
#pragma unroll
        for (int j = 0; j < 8; j++) {
            unsigned long long ss = pack2(sx[w][j][k]);
            ffma2(acc[j][0], ss, wv.x);
            ffma2(acc[j][1], ss, wv.y);
        }
    }
    float4 bv = ((const float4*)b_lin)[l];
    int h = l >> 3, j0 = (l & 7) * 4;
    const float* at  = att + h * 64 + j0;
    const float* at2 = at + 32;
#pragma unroll
    for (int j = 0; j < 8; j++) {
        int n = base + j;
        if (n >= N) break;
        float4 a = unpack4(acc[j][0], acc[j][1]);
        a.x += bv.x; a.y += bv.y; a.z += bv.z; a.w += bv.w;
        ((uint2*)g_xe16)[n * 32 + l] = pack_h4(a);
        float pi = a.x * at[0]  + a.y * at[1]  + a.z * at[2]  + a.w * at[3];
        float pj = a.x * at2[0] + a.y * at2[1] + a.z * at2[2] + a.w * at2[3];
#pragma unroll
        for (int o = 4; o; o >>= 1) {
            pi += __shfl_down_sync(0xffffffffu, pi, o, 8);
            pj += __shfl_down_sync(0xffffffffu, pj, o, 8);
        }
        if ((l & 7) == 0) { g_ai[n * 4 + h] = pi; g_aj[n * 4 + h] = pj; }
    }
}

__global__ __launch_bounds__(128) void node_h_kernel(const float* __restrict__ x,
                                                     const float* __restrict__ b_lin,
                                                     const float* __restrict__ att,
                                                     int N) {
    __shared__ float sx[4][8][D_];
    int w = threadIdx.x >> 5, l = threadIdx.x & 31;
    int base = blockIdx.x * 32 + w * 8;
    if (base >= N) return;
    float pnx[8];
#pragma unroll
    for (int j = 0; j < 8; j++) {
        int n = min(base + j, N - 1);
        float4 xv = ((const float4*)x)[n * 32 + l];
        ((float4*)sx[w][j])[l] = xv;
        pnx[j] = d4(xv, xv);
    }
#pragma unroll
    for (int o = 16; o; o >>= 1) {
#pragma unroll
        for (int j = 0; j < 8; j++) pnx[j] += __shfl_xor_sync(0xffffffffu, pnx[j], o);
    }
    __syncwarp();
    unsigned long long acc[8][2];
#pragma unroll
    for (int j = 0; j < 8; j++) { acc[j][0] = 0ull; acc[j][1] = 0ull; }
    const ulonglong2* Wt = (const ulonglong2*)g_WtH;
#pragma unroll 2
    for (int k = 0; k < D_; k++) {
        ulonglong2 wv = Wt[k * 32 + l];
#pragma unroll
        for (int j = 0; j < 8; j++) {
            unsigned long long ss = pack2(sx[w][j][k]);
            ffma2(acc[j][0], ss, wv.x);
            ffma2(acc[j][1], ss, wv.y);
        }
    }
    float4 bvv = ((const float4*)b_lin)[l];
    float nb = fmaxf(sqrtf(wsum(d4(bvv, bvv))), MINNORM);
    float nhb = fminf(tanhf(nb), MAXN);
    float4 hb = f4s(bvv, nhb / nb);
    float y2 = nhb * nhb;

    float4 mx[8];
    float pm[8];
#pragma unroll
    for (int j = 0; j < 8; j++) {
        mx[j] = unpack4(acc[j][0], acc[j][1]);
        pm[j] = d4(mx[j], mx[j]);
    }
#pragma unroll
    for (int o = 16; o; o >>= 1) {
#pragma unroll
        for (int j = 0; j < 8; j++) pm[j] += __shfl_xor_sync(0xffffffffu, pm[j], o);
    }
    float nmv[8];
#pragma unroll
    for (int j = 0; j < 8; j++) {
        float n_x = fmaxf(sqrtf(pnx[j]), MINNORM);
        float n_mx = fmaxf(sqrtf(pm[j]), MINNORM);
        nmv[j] = fminf(tanhf(n_mx / n_x * atanhc(n_x)), MAXN);
        float s = nmv[j] / n_mx;
        mx[j] = f4s(mx[j], s);
    }
    float pxy[8];
#pragma unroll
    for (int j = 0; j < 8; j++) pxy[j] = d4(mx[j], hb);
#pragma unroll
    for (int o = 16; o; o >>= 1) {
#pragma unroll
        for (int j = 0; j < 8; j++) pxy[j] += __shfl_xor_sync(0xffffffffu, pxy[j], o);
    }

    int h = l >> 3, j0 = (l & 7) * 4;
    const float* at  = att + h * 64 + j0;
    const float* at2 = at + 32;
#pragma unroll
    for (int j = 0; j < 8; j++) {
        int n = base + j;
        if (n >= N) break;
        float x2 = nmv[j] * nmv[j];
        float xy = pxy[j];
        float A = 1.f + 2.f * xy + y2, B = 1.f - x2;
        float den = fmaxf(1.f + 2.f * xy + x2 * y2, MINNORM);
        float invden = 1.f / den;
        float nxh2 = fmaxf(A * A * x2 + 2.f * A * B * xy + B * B * y2, 0.f)
                     * invden * invden;
        float nxh = fmaxf(sqrtf(nxh2), MINNORM);
        float c = (nxh > MAXN) ? (MAXN / nxh) : 1.f;
        float4 xh = f4s(f4axby(A, mx[j], B, hb), invden * c);
        float nfin = c * nxh;
        float x2f = nfin * nfin;
        ((float4*)g_xh)[n * 32 + l] = xh;
        if (l == 0) g_x2[n] = x2f;
        float ncl = fmaxf(nfin, MINNORM);
        float lsc = atanhc(ncl) / ncl;               // logmap scale
        float4 lx = f4s(xh, lsc);
        ((uint2*)g_lx16)[n * 32 + l] = pack_h4(lx);
        float pi = lx.x * at[0]  + lx.y * at[1]  + lx.z * at[2]  + lx.w * at[3];
        float pj = lx.x * at2[0] + lx.y * at2[1] + lx.z * at2[2] + lx.w * at2[3];
#pragma unroll
        for (int o = 4; o; o >>= 1) {
            pi += __shfl_down_sync(0xffffffffu, pi, o, 8);
            pj += __shfl_down_sync(0xffffffffu, pj, o, 8);
        }
        if ((l & 7) == 0) { g_hi[n * 4 + h] = pi; g_hj[n * 4 + h] = pj; }
    }
}

// ---------------- edge kernel: pass A distances only; pass B both aggregations (fp16) ----------------
__global__ __launch_bounds__(256) void edge_kernel(int N) {
    int w = (blockIdx.x * blockDim.x + threadIdx.x) >> 5;
    int l = threadIdx.x & 31;
    if (w >= N) return;
    int dn = w;
    int beg = g_start[dn], end = g_start[dn + 1];
    int h = l >> 3;
    bool leader = (l & 7) == 0;

    float4 xd  = ((const float4*)g_xh)[dn * 32 + l];
    float  x2d = g_x2[dn];
    float  ai_l = g_ai[dn * 4 + h];
    float  hi_l = g_hi[dn * 4 + h];

    // ---- Pass A: hyperbolic distances only (masked x8) ----
    float sum_d = 0.f;
    for (int k = beg; k < end; k += 8) {
        int e1 = min(k + 1, end - 1), e2 = min(k + 2, end - 1), e3 = min(k + 3, end - 1);
        int e4 = min(k + 4, end - 1), e5 = min(k + 5, end - 1), e6 = min(k + 6, end - 1);
        int e7 = min(k + 7, end - 1);
        int s0 = g_csrc[k],  s1 = g_csrc[e1], s2 = g_csrc[e2], s3 = g_csrc[e3];
        int s4 = g_csrc[e4], s5 = g_csrc[e5], s6 = g_csrc[e6], s7 = g_csrc[e7];
        float p0, p1, p2, p3, p4, p5, p6, p7;
        {
            float4 v0 = ((const float4*)g_xh)[s0 * 32 + l];
            float4 v1 = ((const float4*)g_xh)[s1 * 32 + l];
            float4 v2 = ((const float4*)g_xh)[s2 * 32 + l];
            float4 v3 = ((const float4*)g_xh)[s3 * 32 + l];
            float4 v4 = ((const float4*)g_xh)[s4 * 32 + l];
            float4 v5 = ((const float4*)g_xh)[s5 * 32 + l];
            float4 v6 = ((const float4*)g_xh)[s6 * 32 + l];
            float4 v7 = ((const float4*)g_xh)[s7 * 32 + l];
            p0 = d4(xd, v0); p1 = d4(xd, v1); p2 = d4(xd, v2); p3 = d4(xd, v3);
            p4 = d4(xd, v4); p5 = d4(xd, v5); p6 = d4(xd, v6); p7 = d4(xd, v7);
        }
#pragma unroll
        for (int o = 16; o; o >>= 1) {
            p0 += __shfl_xor_sync(0xffffffffu, p0, o);
            p1 += __shfl_xor_sync(0xffffffffu, p1, o);
            p2 += __shfl_xor_sync(0xffffffffu, p2, o);
            p3 += __shfl_xor_sync(0xffffffffu, p3, o);
            p4 += __shfl_xor_sync(0xffffffffu, p4, o);
            p5 += __shfl_xor_sync(0xffffffffu, p5, o);
            p6 += __shfl_xor_sync(0xffffffffu, p6, o);
            p7 += __shfl_xor_sync(0xffffffffu, p7, o);
        }
        if (l < 8 && k + l < end) {
            float pp = (l & 4) ? ((l & 2) ? ((l & 1) ? p7 : p6) : ((l & 1) ? p5 : p4))
                               : ((l & 2) ? ((l & 1) ? p3 : p2) : ((l & 1) ? p1 : p0));
            int ssel  = (l & 4) ? ((l & 2) ? ((l & 1) ? s7 : s6) : ((l & 1) ? s5 : s4))
                                : ((l & 2) ? ((l & 1) ? s3 : s2) : ((l & 1) ? s1 : s0));
            float yy = g_x2[ssel];
            float A = 1.f - 2.f * pp + yy, B = 1.f - x2d;
            float den = fmaxf(1.f - 2.f * pp + x2d * yy, MINNORM);
            float num2 = fmaxf(A * A * x2d + B * B * yy - 2.f * A * B * pp, 0.f);
            float q = fminf(sqrtf(num2) / den, 1.0f - 1e-7f);
            float edd = (1.f + q) / (1.f - q);       // == exp(2*atanh(q))
            g_de[k + l] = edd;
            sum_d += edd;
        }
    }
    float inv_sd = 1.f / (wsum(sum_d) + 1e-16f);

    // ---- Pass B: BOTH aggregations from fp16 tables (masked x4) ----
    float sum_e = 0.f, sum_h = 0.f;
    float4 acc_e = make_float4(0.f, 0.f, 0.f, 0.f);
    float4 acc_h = make_float4(0.f, 0.f, 0.f, 0.f);
    for (int k = beg; k < end; k += 4) {
        int k1 = min(k + 1, end - 1), k2 = min(k + 2, end - 1), k3 = min(k + 3, end - 1);
        float m1 = (k + 1 < end) ? 1.f : 0.f;
        float m2 = (k + 2 < end) ? 1.f : 0.f;
        float m3 = (k + 3 < end) ? 1.f : 0.f;
        int s0 = g_csrc[k], s1 = g_csrc[k1], s2 = g_csrc[k2], s3 = g_csrc[k3];
        // issue all 8 gathers up front
        uint2 ue0 = ((const uint2*)g_xe16)[s0 * 32 + l];
        uint2 ue1 = ((const uint2*)g_xe16)[s1 * 32 + l];
        uint2 ue2 = ((const uint2*)g_xe16)[s2 * 32 + l];
        uint2 ue3 = ((const uint2*)g_xe16)[s3 * 32 + l];
        uint2 ul0 = ((const uint2*)g_lx16)[s0 * 32 + l];
        uint2 ul1 = ((const uint2*)g_lx16)[s1 * 32 + l];
        uint2 ul2 = ((const uint2*)g_lx16)[s2 * 32 + l];
        uint2 ul3 = ((const uint2*)g_lx16)[s3 * 32 + l];
        float we0 = __expf(lrelu(ai_l + g_aj[s0 * 4 + h]));
        float we1 = __expf(lrelu(ai_l + g_aj[s1 * 4 + h])) * m1;
        float we2 = __expf(lrelu(ai_l + g_aj[s2 * 4 + h])) * m2;
        float we3 = __expf(lrelu(ai_l + g_aj[s3 * 4 + h])) * m3;
        float d0 = g_de[k]  * inv_sd, d1 = g_de[k1] * inv_sd;
        float d2 = g_de[k2] * inv_sd, d3 = g_de[k3] * inv_sd;
        float a0 = __expf(lrelu((hi_l + g_hj[s0 * 4 + h]) * d0));
        float a1 = __expf(lrelu((hi_l + g_hj[s1 * 4 + h]) * d1)) * m1;
        float a2 = __expf(lrelu((hi_l + g_hj[s2 * 4 + h]) * d2)) * m2;
        float a3 = __expf(lrelu((hi_l + g_hj[s3 * 4 + h]) * d3)) * m3;
        if (leader) { sum_e += we0 + we1 + we2 + we3; sum_h += a0 + a1 + a2 + a3; }
        float4 e0 = unpack_h4(ue0), e1 = unpack_h4(ue1);
        float4 e2 = unpack_h4(ue2), e3 = unpack_h4(ue3);
        float4 l0 = unpack_h4(ul0), l1 = unpack_h4(ul1);
        float4 l2 = unpack_h4(ul2), l3 = unpack_h4(ul3);
        acc_e.x = fmaf(we0, e0.x, fmaf(we1, e1.x, fmaf(we2, e2.x, fmaf(we3, e3.x, acc_e.x))));
        acc_e.y = fmaf(we0, e0.y, fmaf(we1, e1.y, fmaf(we2, e2.y, fmaf(we3, e3.y, acc_e.y))));
        acc_e.z = fmaf(we0, e0.z, fmaf(we1, e1.z, fmaf(we2, e2.z, fmaf(we3, e3.z, acc_e.z))));
        acc_e.w = fmaf(we0, e0.w, fmaf(we1, e1.w, fmaf(we2, e2.w, fmaf(we3, e3.w, acc_e.w))));
        acc_h.x = fmaf(a0, l0.x, fmaf(a1, l1.x, fmaf(a2, l2.x, fmaf(a3, l3.x, acc_h.x))));
        acc_h.y = fmaf(a0, l0.y, fmaf(a1, l1.y, fmaf(a2, l2.y, fmaf(a3, l3.y, acc_h.y))));
        acc_h.z = fmaf(a0, l0.z, fmaf(a1, l1.z, fmaf(a2, l2.z, fmaf(a3, l3.z, acc_h.z))));
        acc_h.w = fmaf(a0, l0.w, fmaf(a1, l1.w, fmaf(a2, l2.w, fmaf(a3, l3.w, acc_h.w))));
    }

    float se = __shfl_sync(0xffffffffu, sum_e, h << 3);
    float sh = __shfl_sync(0xffffffffu, sum_h, h << 3);
    float inv_se = 1.f / (se + 1e-16f);
    float inv_sh = 1.f / (sh + 1e-16f);

    ((float4*)g_agg_e)[dn * 32 + l] = f4s(acc_e, inv_se);
    ((float4*)g_agg_h)[dn * 32 + l] = f4s(acc_h, inv_sh);
}

// ---------------- finalize kernel (warp per node; scalar-norm algebra) ----------------
__global__ __launch_bounds__(256) void finalize_kernel(const float* __restrict__ b_e,
                                                       const float* __restrict__ b_h,
                                                       const float* __restrict__ att_hf,
                                                       const float* __restrict__ att_ef,
                                                       float* __restrict__ out, int N) {
    int w = (blockIdx.x * blockDim.x + threadIdx.x) >> 5;
    int l = threadIdx.x & 31;
    if (w >= N) return;
    int n = w;
    float4 ae = ((const float4*)g_agg_e)[n * 32 + l];
    float4 ah = ((const float4*)g_agg_h)[n * 32 + l];
    float4 be = ((const float4*)b_e)[l];
    float4 eo = make_float4(fmaxf(ae.x + be.x, 0.f), fmaxf(ae.y + be.y, 0.f),
                            fmaxf(ae.z + be.z, 0.f), fmaxf(ae.w + be.w, 0.f));
    float4 bh = ((const float4*)b_h)[l];
    float4 ot = make_float4(fmaxf(ah.x + bh.x, 0.f), fmaxf(ah.y + bh.y, 0.f),
                            fmaxf(ah.z + bh.z, 0.f), fmaxf(ah.w + bh.w, 0.f));
    float nt = fmaxf(sqrtf(wsum(d4(ot, ot))), MINNORM);
    float nho = fminf(tanhf(nt), MAXN);
    float4 ho = f4s(ot, nho / nt);
    float x2 = nho * nho;
    float ne2 = wsum(d4(eo, eo));
    float ne = fmaxf(sqrtf(ne2), MINNORM);
    float nye = fminf(tanhf(ne), MAXN);
    float4 ye = f4s(eo, nye / ne);
    float y2 = nye * nye;
    float xy = wsum(d4(ho, ye));
    float A = 1.f - 2.f * xy + y2, B = 1.f - x2;
    float den = fmaxf(1.f - 2.f * xy + x2 * y2, MINNORM);
    float num2 = fmaxf(A * A * x2 + B * B * y2 - 2.f * A * B * xy, 0.f);
    float r = 2.f * atanhc(sqrtf(num2) / den) * att_hf[0];
    float ny = fmaxf(nye, MINNORM);
    float t3 = tanhf(r * atanhc(ny));
    float kxe = t3 / ny;
    float nxe2 = fabsf(kxe) * nye;
    float c2 = (nxe2 > MAXN) ? (MAXN / fmaxf(nxe2, MINNORM)) : 1.f;
    float kxe2 = kxe * c2;
    float4 xe2 = f4s(ye, kxe2);
    float nxe2c = nxe2 * c2;
    float y2b = nxe2c * nxe2c;
    float xyb = xy * kxe2;
    float A2 = 1.f + 2.f * xyb + y2b, B2 = 1.f - x2;
    float den2 = fmaxf(1.f + 2.f * xyb + x2 * y2b, MINNORM);
    float invden2 = 1.f / den2;
    float nhf2 = fmaxf(A2 * A2 * x2 + 2.f * A2 * B2 * xyb + B2 * B2 * y2b, 0.f)
                 * invden2 * invden2;
    float nhf = fmaxf(sqrtf(nhf2), MINNORM);
    float c3 = (nhf > MAXN) ? (MAXN / nhf) : 1.f;
    float4 hf = f4s(f4axby(A2, ho, B2, xe2), invden2 * c3);
    float nclh = fmaxf(nho, MINNORM);
    float alh = atanhc(nclh);
    float kl = alh / nclh;
    float4 lh = f4s(ho, kl);
    float dot_ho_eo = xy * ne / nye;
    float de = (alh * alh - 2.f * kl * dot_ho_eo + ne2) * att_ef[0];
    float4 ef = make_float4(eo.x + de * lh.x, eo.y + de * lh.y,
                            eo.z + de * lh.z, eo.w + de * lh.w);
    ((float4*)out)[n * 32 + l] = hf;
    ((float4*)out)[(size_t)N * 32 + n * 32 + l] = ef;
}

// ---------------- launch: node_e / node_h / CSR on three concurrent streams ----------------
extern "C" void kernel_launch(void* const* d_in, const int* in_sizes, int n_in,
                              void* d_out, int out_size) {
    const float* x_e      = (const float*)d_in[0];
    const float* x_h      = (const float*)d_in[1];
    const int*   ei       = (const int*)d_in[2];
    const float* W_e      = (const float*)d_in[3];
    const float* b_lin_e  = (const float*)d_in[4];
    const float* att_e    = (const float*)d_in[5];
    const float* b_e      = (const float*)d_in[6];
    const float* W_h      = (const float*)d_in[7];
    const float* b_lin_h  = (const float*)d_in[8];
    const float* att_h    = (const float*)d_in[9];
    const float* b_h      = (const float*)d_in[10];
    const float* att_hf   = (const float*)d_in[11];
    const float* att_ef   = (const float*)d_in[12];
    float* out = (float*)d_out;

    int N  = in_sizes[0] / D_;
    int E  = in_sizes[2] / 2;
    int EP = E + N;
    int nsb = (N + 255) / 256;
    int ninit = (N > 2 * D_ * D_) ? N : 2 * D_ * D_;

    static cudaStream_t s2 = nullptr, s3 = nullptr;
    static cudaEvent_t evFork = nullptr, evJoin2 = nullptr, evJoin3 = nullptr;
    if (s2 == nullptr) {
        cudaStreamCreateWithFlags(&s2, cudaStreamNonBlocking);
        cudaStreamCreateWithFlags(&s3, cudaStreamNonBlocking);
        cudaEventCreateWithFlags(&evFork, cudaEventDisableTiming);
        cudaEventCreateWithFlags(&evJoin2, cudaEventDisableTiming);
        cudaEventCreateWithFlags(&evJoin3, cudaEventDisableTiming);
    }

    // main stream: init (weights + deg zero)
    init_kernel<<<(ninit + 255) / 256, 256>>>(W_e, W_h, N);
    cudaEventRecord(evFork, 0);

    // side stream s2: CSR build chain
    cudaStreamWaitEvent(s2, evFork, 0);
    count_kernel<<<(EP + 255) / 256, 256, 0, s2>>>(ei, E, EP);
    scan1_kernel<<<nsb, 256, 0, s2>>>(N);
    scan2_kernel<<<1, 256, 0, s2>>>(nsb);
    scan3_kernel<<<(N + 255) / 256, 256, 0, s2>>>(N, EP);
    scatter_kernel<<<(EP + 255) / 256, 256, 0, s2>>>(ei, E, EP);
    cudaEventRecord(evJoin2, s2);

    // side stream s3: hyperbolic node kernel (concurrent with node_e)
    cudaStreamWaitEvent(s3, evFork, 0);
    node_h_kernel<<<(N + 31) / 32, 128, 0, s3>>>(x_h, b_lin_h, att_h, N);
    cudaEventRecord(evJoin3, s3);

    // main stream: euclidean node kernel
    node_e_kernel<<<(N + 31) / 32, 128>>>(x_e, b_lin_e, att_e, N);

    // join all, then edge aggregation, then finalize
    cudaStreamWaitEvent(0, evJoin2, 0);
    cudaStreamWaitEvent(0, evJoin3, 0);
    edge_kernel<<<(N * 32 + 255) / 256, 256>>>(N);
    finalize_kernel<<<(N * 32 + 255) / 256, 256>>>(b_e, b_h, att_hf, att_ef, out, N);
}

// round 17
// speedup vs baseline: 1.1219x; 1.0290x over previous
#include <cuda_runtime.h>
#include <cuda_fp16.h>
#include <math.h>

#define D_ 128
#define NMAX 50016
#define EPMAX 550032
#define MAXN 0.99999f
#define MINNORM 1e-15f

// ---------------- scratch ----------------
__device__ __half g_xh16[NMAX * D_];
__device__ __half g_xe16[NMAX * D_];
__device__ __half g_lx16[NMAX * D_];
__device__ float  g_agg_e[NMAX * D_];
__device__ float  g_agg_h[NMAX * D_];
__device__ float  g_ai[NMAX * 4];
__device__ float  g_aj[NMAX * 4];
__device__ float  g_hi[NMAX * 4];
__device__ float  g_hj[NMAX * 4];
__device__ float  g_x2[NMAX];
__device__ float  g_de[EPMAX];      // exp(distance)
__device__ float  g_WtE[D_ * D_];
__device__ float  g_WtH[D_ * D_];
__device__ int    g_deg[NMAX];
__device__ int    g_cur[NMAX];
__device__ int    g_start[NMAX + 1];
__device__ int    g_csrc[EPMAX];
__device__ int    g_bsum[256];

// ---------------- helpers ----------------
__device__ __forceinline__ float atanhc(float x) {
    x = fminf(fmaxf(x, -1.0f + 1e-7f), 1.0f - 1e-7f);
    return atanhf(x);
}
__device__ __forceinline__ float wsum(float v) {
#pragma unroll
    for (int o = 16; o; o >>= 1) v += __shfl_xor_sync(0xffffffffu, v, o);
    return v;
}
__device__ __forceinline__ float d4(float4 a, float4 b) {
    return a.x * b.x + a.y * b.y + a.z * b.z + a.w * b.w;
}
__device__ __forceinline__ float4 f4s(float4 a, float s) {
    return make_float4(a.x * s, a.y * s, a.z * s, a.w * s);
}
__device__ __forceinline__ float4 f4axby(float a, float4 x, float b, float4 y) {
    return make_float4(a * x.x + b * y.x, a * x.y + b * y.y,
                       a * x.z + b * y.z, a * x.w + b * y.w);
}
__device__ __forceinline__ float lrelu(float v) { return v >= 0.f ? v : 0.2f * v; }

// pack float4 -> 4x fp16 in uint2
__device__ __forceinline__ uint2 pack_h4(float4 v) {
    __half2 h01 = __floats2half2_rn(v.x, v.y);
    __half2 h23 = __floats2half2_rn(v.z, v.w);
    uint2 u;
    u.x = *reinterpret_cast<unsigned*>(&h01);
    u.y = *reinterpret_cast<unsigned*>(&h23);
    return u;
}
// unpack uint2 (4x fp16) -> float4
__device__ __forceinline__ float4 unpack_h4(uint2 u) {
    __half2 h01 = *reinterpret_cast<__half2*>(&u.x);
    __half2 h23 = *reinterpret_cast<__half2*>(&u.y);
    float2 f01 = __half22float2(h01);
    float2 f23 = __half22float2(h23);
    return make_float4(f01.x, f01.y, f23.x, f23.y);
}

// packed f32x2 helpers (Blackwell FFMA2)
__device__ __forceinline__ void ffma2(unsigned long long &acc,
                                      unsigned long long a, unsigned long long b) {
    asm("fma.rn.f32x2 %0, %1, %2, %3;" : "=l"(acc) : "l"(a), "l"(b), "l"(acc));
}
__device__ __forceinline__ unsigned long long pack2(float s) {
    unsigned u = __float_as_uint(s);
    unsigned long long r;
    asm("mov.b64 %0, {%1, %1};" : "=l"(r) : "r"(u));
    return r;
}
__device__ __forceinline__ float4 unpack4(unsigned long long lo, unsigned long long hi) {
    float4 v;
    asm("mov.b64 {%0, %1}, %2;" : "=f"(v.x), "=f"(v.y) : "l"(lo));
    asm("mov.b64 {%0, %1}, %2;" : "=f"(v.z), "=f"(v.w) : "l"(hi));
    return v;
}

// ---------------- init: zero degrees + transpose weights ----------------
__global__ __launch_bounds__(256) void init_kernel(const float* __restrict__ We,
                                                   const float* __restrict__ Wh, int N) {
    int i = blockIdx.x * blockDim.x + threadIdx.x;
    if (i < N) g_deg[i] = 0;
    if (i < 2 * D_ * D_) {
        int m = i >> 14;
        int k = (i >> 7) & 127;
        int c = i & 127;
        if (m == 0) g_WtE[k * D_ + c] = We[c * D_ + k];
        else        g_WtH[k * D_ + c] = Wh[c * D_ + k];
    }
}

__global__ __launch_bounds__(256) void count_kernel(const int* __restrict__ ei, int E, int EP) {
    int e = blockIdx.x * blockDim.x + threadIdx.x;
    if (e >= EP) return;
    int dn = (e < E) ? ei[E + e] : (e - E);
    atomicAdd(&g_deg[dn], 1);
}

__global__ __launch_bounds__(256) void scan1_kernel(int N) {
    __shared__ int sm[256];
    int i = blockIdx.x * 256 + threadIdx.x;
    int v = (i < N) ? g_deg[i] : 0;
    sm[threadIdx.x] = v;
    __syncthreads();
#pragma unroll
    for (int d = 1; d < 256; d <<= 1) {
        int t = (threadIdx.x >= d) ? sm[threadIdx.x - d] : 0;
        __syncthreads();
        sm[threadIdx.x] += t;
        __syncthreads();
    }
    if (i < N) g_start[i] = sm[threadIdx.x] - v;
    if (threadIdx.x == 255) g_bsum[blockIdx.x] = sm[255];
}

__global__ __launch_bounds__(256) void scan2_kernel(int nb) {
    __shared__ int sm[256];
    int v = (threadIdx.x < nb) ? g_bsum[threadIdx.x] : 0;
    sm[threadIdx.x] = v;
    __syncthreads();
#pragma unroll
    for (int d = 1; d < 256; d <<= 1) {
        int t = (threadIdx.x >= d) ? sm[threadIdx.x - d] : 0;
        __syncthreads();
        sm[threadIdx.x] += t;
        __syncthreads();
    }
    g_bsum[threadIdx.x] = sm[threadIdx.x] - v;
}

__global__ __launch_bounds__(256) void scan3_kernel(int N, int EP) {
    int i = blockIdx.x * 256 + threadIdx.x;
    if (i < N) { g_start[i] += g_bsum[i >> 8]; g_cur[i] = 0; }
    if (i == 0) g_start[N] = EP;
}

__global__ __launch_bounds__(256) void scatter_kernel(const int* __restrict__ ei, int E, int EP) {
    int e = blockIdx.x * blockDim.x + threadIdx.x;
    if (e >= EP) return;
    int s, dn;
    if (e < E) { s = ei[e]; dn = ei[E + e]; } else { s = dn = e - E; }
    int pos = atomicAdd(&g_cur[dn], 1);
    g_csrc[g_start[dn] + pos] = s;
}

// ---------------- node kernels: 8 nodes/warp ----------------
__global__ __launch_bounds__(128) void node_e_kernel(const float* __restrict__ x,
                                                     const float* __restrict__ b_lin,
                                                     const float* __restrict__ att,
                                                     int N) {
    __shared__ float sx[4][8][D_];
    int w = threadIdx.x >> 5, l = threadIdx.x & 31;
    int base = blockIdx.x * 32 + w * 8;
    if (base >= N) return;
#pragma unroll
    for (int j = 0; j < 8; j++) {
        int n = min(base + j, N - 1);
        ((float4*)sx[w][j])[l] = ((const float4*)x)[n * 32 + l];
    }
    __syncwarp();
    unsigned long long acc[8][2];
#pragma unroll
    for (int j = 0; j < 8; j++) { acc[j][0] = 0ull; acc[j][1] = 0ull; }
    const ulonglong2* Wt = (const ulonglong2*)g_WtE;
#pragma unroll 2
    for (int k = 0; k < D_; k++) {
        ulonglong2 wv = Wt[k * 32 + l];
#pragma unroll
        for (int j = 0; j < 8; j++) {
            unsigned long long ss = pack2(sx[w][j][k]);
            ffma2(acc[j][0], ss, wv.x);
            ffma2(acc[j][1], ss, wv.y);
        }
    }
    float4 bv = ((const float4*)b_lin)[l];
    int h = l >> 3, j0 = (l & 7) * 4;
    const float* at  = att + h * 64 + j0;
    const float* at2 = at + 32;
#pragma unroll
    for (int j = 0; j < 8; j++) {
        int n = base + j;
        if (n >= N) break;
        float4 a = unpack4(acc[j][0], acc[j][1]);
        a.x += bv.x; a.y += bv.y; a.z += bv.z; a.w += bv.w;
        ((uint2*)g_xe16)[n * 32 + l] = pack_h4(a);
        float pi = a.x * at[0]  + a.y * at[1]  + a.z * at[2]  + a.w * at[3];
        float pj = a.x * at2[0] + a.y * at2[1] + a.z * at2[2] + a.w * at2[3];
#pragma unroll
        for (int o = 4; o; o >>= 1) {
            pi += __shfl_down_sync(0xffffffffu, pi, o, 8);
            pj += __shfl_down_sync(0xffffffffu, pj, o, 8);
        }
        if ((l & 7) == 0) { g_ai[n * 4 + h] = pi; g_aj[n * 4 + h] = pj; }
    }
}

__global__ __launch_bounds__(128) void node_h_kernel(const float* __restrict__ x,
                                                     const float* __restrict__ b_lin,
                                                     const float* __restrict__ att,
                                                     int N) {
    __shared__ float sx[4][8][D_];
    int w = threadIdx.x >> 5, l = threadIdx.x & 31;
    int base = blockIdx.x * 32 + w * 8;
    if (base >= N) return;
    float pnx[8];
#pragma unroll
    for (int j = 0; j < 8; j++) {
        int n = min(base + j, N - 1);
        float4 xv = ((const float4*)x)[n * 32 + l];
        ((float4*)sx[w][j])[l] = xv;
        pnx[j] = d4(xv, xv);
    }
#pragma unroll
    for (int o = 16; o; o >>= 1) {
#pragma unroll
        for (int j = 0; j < 8; j++) pnx[j] += __shfl_xor_sync(0xffffffffu, pnx[j], o);
    }
    __syncwarp();
    unsigned long long acc[8][2];
#pragma unroll
    for (int j = 0; j < 8; j++) { acc[j][0] = 0ull; acc[j][1] = 0ull; }
    const ulonglong2* Wt = (const ulonglong2*)g_WtH;
#pragma unroll 2
    for (int k = 0; k < D_; k++) {
        ulonglong2 wv = Wt[k * 32 + l];
#pragma unroll
        for (int j = 0; j < 8; j++) {
            unsigned long long ss = pack2(sx[w][j][k]);
            ffma2(acc[j][0], ss, wv.x);
            ffma2(acc[j][1], ss, wv.y);
        }
    }
    float4 bvv = ((const float4*)b_lin)[l];
    float nb = fmaxf(sqrtf(wsum(d4(bvv, bvv))), MINNORM);
    float nhb = fminf(tanhf(nb), MAXN);
    float4 hb = f4s(bvv, nhb / nb);
    float y2 = nhb * nhb;

    float4 mx[8];
    float pm[8];
#pragma unroll
    for (int j = 0; j < 8; j++) {
        mx[j] = unpack4(acc[j][0], acc[j][1]);
        pm[j] = d4(mx[j], mx[j]);
    }
#pragma unroll
    for (int o = 16; o; o >>= 1) {
#pragma unroll
        for (int j = 0; j < 8; j++) pm[j] += __shfl_xor_sync(0xffffffffu, pm[j], o);
    }
    float nmv[8];
#pragma unroll
    for (int j = 0; j < 8; j++) {
        float n_x = fmaxf(sqrtf(pnx[j]), MINNORM);
        float n_mx = fmaxf(sqrtf(pm[j]), MINNORM);
        nmv[j] = fminf(tanhf(n_mx / n_x * atanhc(n_x)), MAXN);
        float s = nmv[j] / n_mx;
        mx[j] = f4s(mx[j], s);
    }
    float pxy[8];
#pragma unroll
    for (int j = 0; j < 8; j++) pxy[j] = d4(mx[j], hb);
#pragma unroll
    for (int o = 16; o; o >>= 1) {
#pragma unroll
        for (int j = 0; j < 8; j++) pxy[j] += __shfl_xor_sync(0xffffffffu, pxy[j], o);
    }

    int h = l >> 3, j0 = (l & 7) * 4;
    const float* at  = att + h * 64 + j0;
    const float* at2 = at + 32;
#pragma unroll
    for (int j = 0; j < 8; j++) {
        int n = base + j;
        if (n >= N) break;
        float x2 = nmv[j] * nmv[j];
        float xy = pxy[j];
        float A = 1.f + 2.f * xy + y2, B = 1.f - x2;
        float den = fmaxf(1.f + 2.f * xy + x2 * y2, MINNORM);
        float invden = 1.f / den;
        float nxh2 = fmaxf(A * A * x2 + 2.f * A * B * xy + B * B * y2, 0.f)
                     * invden * invden;
        float nxh = fmaxf(sqrtf(nxh2), MINNORM);
        float c = (nxh > MAXN) ? (MAXN / nxh) : 1.f;
        float4 xh = f4s(f4axby(A, mx[j], B, hb), invden * c);
        float nfin = c * nxh;
        float x2f = nfin * nfin;
        ((uint2*)g_xh16)[n * 32 + l] = pack_h4(xh);
        if (l == 0) g_x2[n] = x2f;
        float ncl = fmaxf(nfin, MINNORM);
        float lsc = atanhc(ncl) / ncl;               // logmap scale
        float4 lx = f4s(xh, lsc);
        ((uint2*)g_lx16)[n * 32 + l] = pack_h4(lx);
        float pi = lx.x * at[0]  + lx.y * at[1]  + lx.z * at[2]  + lx.w * at[3];
        float pj = lx.x * at2[0] + lx.y * at2[1] + lx.z * at2[2] + lx.w * at2[3];
#pragma unroll
        for (int o = 4; o; o >>= 1) {
            pi += __shfl_down_sync(0xffffffffu, pi, o, 8);
            pj += __shfl_down_sync(0xffffffffu, pj, o, 8);
        }
        if ((l & 7) == 0) { g_hi[n * 4 + h] = pi; g_hj[n * 4 + h] = pj; }
    }
}

// ---------------- edge kernel: pass A distances (fp16 xh); pass B aggregations (fp16) ----------------
__global__ __launch_bounds__(256) void edge_kernel(int N) {
    int w = (blockIdx.x * blockDim.x + threadIdx.x) >> 5;
    int l = threadIdx.x & 31;
    if (w >= N) return;
    int dn = w;
    int beg = g_start[dn], end = g_start[dn + 1];
    int h = l >> 3;
    bool leader = (l & 7) == 0;

    float4 xd  = unpack_h4(((const uint2*)g_xh16)[dn * 32 + l]);
    float  x2d = g_x2[dn];
    float  ai_l = g_ai[dn * 4 + h];
    float  hi_l = g_hi[dn * 4 + h];

    // ---- Pass A: hyperbolic distances only (masked x8, fp16 gathers) ----
    float sum_d = 0.f;
    for (int k = beg; k < end; k += 8) {
        int e1 = min(k + 1, end - 1), e2 = min(k + 2, end - 1), e3 = min(k + 3, end - 1);
        int e4 = min(k + 4, end - 1), e5 = min(k + 5, end - 1), e6 = min(k + 6, end - 1);
        int e7 = min(k + 7, end - 1);
        int s0 = g_csrc[k],  s1 = g_csrc[e1], s2 = g_csrc[e2], s3 = g_csrc[e3];
        int s4 = g_csrc[e4], s5 = g_csrc[e5], s6 = g_csrc[e6], s7 = g_csrc[e7];
        float p0, p1, p2, p3, p4, p5, p6, p7;
        {
            uint2 u0 = ((const uint2*)g_xh16)[s0 * 32 + l];
            uint2 u1 = ((const uint2*)g_xh16)[s1 * 32 + l];
            uint2 u2 = ((const uint2*)g_xh16)[s2 * 32 + l];
            uint2 u3 = ((const uint2*)g_xh16)[s3 * 32 + l];
            uint2 u4 = ((const uint2*)g_xh16)[s4 * 32 + l];
            uint2 u5 = ((const uint2*)g_xh16)[s5 * 32 + l];
            uint2 u6 = ((const uint2*)g_xh16)[s6 * 32 + l];
            uint2 u7 = ((const uint2*)g_xh16)[s7 * 32 + l];
            p0 = d4(xd, unpack_h4(u0)); p1 = d4(xd, unpack_h4(u1));
            p2 = d4(xd, unpack_h4(u2)); p3 = d4(xd, unpack_h4(u3));
            p4 = d4(xd, unpack_h4(u4)); p5 = d4(xd, unpack_h4(u5));
            p6 = d4(xd, unpack_h4(u6)); p7 = d4(xd, unpack_h4(u7));
        }
#pragma unroll
        for (int o = 16; o; o >>= 1) {
            p0 += __shfl_xor_sync(0xffffffffu, p0, o);
            p1 += __shfl_xor_sync(0xffffffffu, p1, o);
            p2 += __shfl_xor_sync(0xffffffffu, p2, o);
            p3 += __shfl_xor_sync(0xffffffffu, p3, o);
            p4 += __shfl_xor_sync(0xffffffffu, p4, o);
            p5 += __shfl_xor_sync(0xffffffffu, p5, o);
            p6 += __shfl_xor_sync(0xffffffffu, p6, o);
            p7 += __shfl_xor_sync(0xffffffffu, p7, o);
        }
        if (l < 8 && k + l < end) {
            float pp = (l & 4) ? ((l & 2) ? ((l & 1) ? p7 : p6) : ((l & 1) ? p5 : p4))
                               : ((l & 2) ? ((l & 1) ? p3 : p2) : ((l & 1) ? p1 : p0));
            int ssel  = (l & 4) ? ((l & 2) ? ((l & 1) ? s7 : s6) : ((l & 1) ? s5 : s4))
                                : ((l & 2) ? ((l & 1) ? s3 : s2) : ((l & 1) ? s1 : s0));
            float yy = g_x2[ssel];
            float A = 1.f - 2.f * pp + yy, B = 1.f - x2d;
            float den = fmaxf(1.f - 2.f * pp + x2d * yy, MINNORM);
            float num2 = fmaxf(A * A * x2d + B * B * yy - 2.f * A * B * pp, 0.f);
            float q = fminf(sqrtf(num2) / den, 1.0f - 1e-7f);
            float edd = (1.f + q) / (1.f - q);       // == exp(2*atanh(q))
            g_de[k + l] = edd;
            sum_d += edd;
        }
    }
    float inv_sd = 1.f / (wsum(sum_d) + 1e-16f);

    // ---- Pass B: BOTH aggregations from fp16 tables (masked x4) ----
    float sum_e = 0.f, sum_h = 0.f;
    float4 acc_e = make_float4(0.f, 0.f, 0.f, 0.f);
    float4 acc_h = make_float4(0.f, 0.f, 0.f, 0.f);
    for (int k = beg; k < end; k += 4) {
        int k1 = min(k + 1, end - 1), k2 = min(k + 2, end - 1), k3 = min(k + 3, end - 1);
        float m1 = (k + 1 < end) ? 1.f : 0.f;
        float m2 = (k + 2 < end) ? 1.f : 0.f;
        float m3 = (k + 3 < end) ? 1.f : 0.f;
        int s0 = g_csrc[k], s1 = g_csrc[k1], s2 = g_csrc[k2], s3 = g_csrc[k3];
        uint2 ue0 = ((const uint2*)g_xe16)[s0 * 32 + l];
        uint2 ue1 = ((const uint2*)g_xe16)[s1 * 32 + l];
        uint2 ue2 = ((const uint2*)g_xe16)[s2 * 32 + l];
        uint2 ue3 = ((const uint2*)g_xe16)[s3 * 32 + l];
        uint2 ul0 = ((const uint2*)g_lx16)[s0 * 32 + l];
        uint2 ul1 = ((const uint2*)g_lx16)[s1 * 32 + l];
        uint2 ul2 = ((const uint2*)g_lx16)[s2 * 32 + l];
        uint2 ul3 = ((const uint2*)g_lx16)[s3 * 32 + l];
        float we0 = __expf(lrelu(ai_l + g_aj[s0 * 4 + h]));
        float we1 = __expf(lrelu(ai_l + g_aj[s1 * 4 + h])) * m1;
        float we2 = __expf(lrelu(ai_l + g_aj[s2 * 4 + h])) * m2;
        float we3 = __expf(lrelu(ai_l + g_aj[s3 * 4 + h])) * m3;
        float d0 = g_de[k]  * inv_sd, d1 = g_de[k1] * inv_sd;
        float d2 = g_de[k2] * inv_sd, d3 = g_de[k3] * inv_sd;
        float a0 = __expf(lrelu((hi_l + g_hj[s0 * 4 + h]) * d0));
        float a1 = __expf(lrelu((hi_l + g_hj[s1 * 4 + h]) * d1)) * m1;
        float a2 = __expf(lrelu((hi_l + g_hj[s2 * 4 + h]) * d2)) * m2;
        float a3 = __expf(lrelu((hi_l + g_hj[s3 * 4 + h]) * d3)) * m3;
        if (leader) { sum_e += we0 + we1 + we2 + we3; sum_h += a0 + a1 + a2 + a3; }
        float4 e0 = unpack_h4(ue0), e1 = unpack_h4(ue1);
        float4 e2 = unpack_h4(ue2), e3 = unpack_h4(ue3);
        float4 l0 = unpack_h4(ul0), l1 = unpack_h4(ul1);
        float4 l2 = unpack_h4(ul2), l3 = unpack_h4(ul3);
        acc_e.x = fmaf(we0, e0.x, fmaf(we1, e1.x, fmaf(we2, e2.x, fmaf(we3, e3.x, acc_e.x))));
        acc_e.y = fmaf(we0, e0.y, fmaf(we1, e1.y, fmaf(we2, e2.y, fmaf(we3, e3.y, acc_e.y))));
        acc_e.z = fmaf(we0, e0.z, fmaf(we1, e1.z, fmaf(we2, e2.z, fmaf(we3, e3.z, acc_e.z))));
        acc_e.w = fmaf(we0, e0.w, fmaf(we1, e1.w, fmaf(we2, e2.w, fmaf(we3, e3.w, acc_e.w))));
        acc_h.x = fmaf(a0, l0.x, fmaf(a1, l1.x, fmaf(a2, l2.x, fmaf(a3, l3.x, acc_h.x))));
        acc_h.y = fmaf(a0, l0.y, fmaf(a1, l1.y, fmaf(a2, l2.y, fmaf(a3, l3.y, acc_h.y))));
        acc_h.z = fmaf(a0, l0.z, fmaf(a1, l1.z, fmaf(a2, l2.z, fmaf(a3, l3.z, acc_h.z))));
        acc_h.w = fmaf(a0, l0.w, fmaf(a1, l1.w, fmaf(a2, l2.w, fmaf(a3, l3.w, acc_h.w))));
    }

    float se = __shfl_sync(0xffffffffu, sum_e, h << 3);
    float sh = __shfl_sync(0xffffffffu, sum_h, h << 3);
    float inv_se = 1.f / (se + 1e-16f);
    float inv_sh = 1.f / (sh + 1e-16f);

    ((float4*)g_agg_e)[dn * 32 + l] = f4s(acc_e, inv_se);
    ((float4*)g_agg_h)[dn * 32 + l] = f4s(acc_h, inv_sh);
}

// ---------------- finalize kernel (warp per node; scalar-norm algebra) ----------------
__global__ __launch_bounds__(256) void finalize_kernel(const float* __restrict__ b_e,
                                                       const float* __restrict__ b_h,
                                                       const float* __restrict__ att_hf,
                                                       const float* __restrict__ att_ef,
                                                       float* __restrict__ out, int N) {
    int w = (blockIdx.x * blockDim.x + threadIdx.x) >> 5;
    int l = threadIdx.x & 31;
    if (w >= N) return;
    int n = w;
    float4 ae = ((const float4*)g_agg_e)[n * 32 + l];
    float4 ah = ((const float4*)g_agg_h)[n * 32 + l];
    float4 be = ((const float4*)b_e)[l];
    float4 eo = make_float4(fmaxf(ae.x + be.x, 0.f), fmaxf(ae.y + be.y, 0.f),
                            fmaxf(ae.z + be.z, 0.f), fmaxf(ae.w + be.w, 0.f));
    float4 bh = ((const float4*)b_h)[l];
    float4 ot = make_float4(fmaxf(ah.x + bh.x, 0.f), fmaxf(ah.y + bh.y, 0.f),
                            fmaxf(ah.z + bh.z, 0.f), fmaxf(ah.w + bh.w, 0.f));
    float nt = fmaxf(sqrtf(wsum(d4(ot, ot))), MINNORM);
    float nho = fminf(tanhf(nt), MAXN);
    float4 ho = f4s(ot, nho / nt);
    float x2 = nho * nho;
    float ne2 = wsum(d4(eo, eo));
    float ne = fmaxf(sqrtf(ne2), MINNORM);
    float nye = fminf(tanhf(ne), MAXN);
    float4 ye = f4s(eo, nye / ne);
    float y2 = nye * nye;
    float xy = wsum(d4(ho, ye));
    float A = 1.f - 2.f * xy + y2, B = 1.f - x2;
    float den = fmaxf(1.f - 2.f * xy + x2 * y2, MINNORM);
    float num2 = fmaxf(A * A * x2 + B * B * y2 - 2.f * A * B * xy, 0.f);
    float r = 2.f * atanhc(sqrtf(num2) / den) * att_hf[0];
    float ny = fmaxf(nye, MINNORM);
    float t3 = tanhf(r * atanhc(ny));
    float kxe = t3 / ny;
    float nxe2 = fabsf(kxe) * nye;
    float c2 = (nxe2 > MAXN) ? (MAXN / fmaxf(nxe2, MINNORM)) : 1.f;
    float kxe2 = kxe * c2;
    float4 xe2 = f4s(ye, kxe2);
    float nxe2c = nxe2 * c2;
    float y2b = nxe2c * nxe2c;
    float xyb = xy * kxe2;
    float A2 = 1.f + 2.f * xyb + y2b, B2 = 1.f - x2;
    float den2 = fmaxf(1.f + 2.f * xyb + x2 * y2b, MINNORM);
    float invden2 = 1.f / den2;
    float nhf2 = fmaxf(A2 * A2 * x2 + 2.f * A2 * B2 * xyb + B2 * B2 * y2b, 0.f)
                 * invden2 * invden2;
    float nhf = fmaxf(sqrtf(nhf2), MINNORM);
    float c3 = (nhf > MAXN) ? (MAXN / nhf) : 1.f;
    float4 hf = f4s(f4axby(A2, ho, B2, xe2), invden2 * c3);
    float nclh = fmaxf(nho, MINNORM);
    float alh = atanhc(nclh);
    float kl = alh / nclh;
    float4 lh = f4s(ho, kl);
    float dot_ho_eo = xy * ne / nye;
    float de = (alh * alh - 2.f * kl * dot_ho_eo + ne2) * att_ef[0];
    float4 ef = make_float4(eo.x + de * lh.x, eo.y + de * lh.y,
                            eo.z + de * lh.z, eo.w + de * lh.w);
    ((float4*)out)[n * 32 + l] = hf;
    ((float4*)out)[(size_t)N * 32 + n * 32 + l] = ef;
}

// ---------------- launch: node_e / node_h / CSR on three concurrent streams ----------------
extern "C" void kernel_launch(void* const* d_in, const int* in_sizes, int n_in,
                              void* d_out, int out_size) {
    const float* x_e      = (const float*)d_in[0];
    const float* x_h      = (const float*)d_in[1];
    const int*   ei       = (const int*)d_in[2];
    const float* W_e      = (const float*)d_in[3];
    const float* b_lin_e  = (const float*)d_in[4];
    const float* att_e    = (const float*)d_in[5];
    const float* b_e      = (const float*)d_in[6];
    const float* W_h      = (const float*)d_in[7];
    const float* b_lin_h  = (const float*)d_in[8];
    const float* att_h    = (const float*)d_in[9];
    const float* b_h      = (const float*)d_in[10];
    const float* att_hf   = (const float*)d_in[11];
    const float* att_ef   = (const float*)d_in[12];
    float* out = (float*)d_out;

    int N  = in_sizes[0] / D_;
    int E  = in_sizes[2] / 2;
    int EP = E + N;
    int nsb = (N + 255) / 256;
    int ninit = (N > 2 * D_ * D_) ? N : 2 * D_ * D_;

    static cudaStream_t s2 = nullptr, s3 = nullptr;
    static cudaEvent_t evFork = nullptr, evJoin2 = nullptr, evJoin3 = nullptr;
    if (s2 == nullptr) {
        cudaStreamCreateWithFlags(&s2, cudaStreamNonBlocking);
        cudaStreamCreateWithFlags(&s3, cudaStreamNonBlocking);
        cudaEventCreateWithFlags(&evFork, cudaEventDisableTiming);
        cudaEventCreateWithFlags(&evJoin2, cudaEventDisableTiming);
        cudaEventCreateWithFlags(&evJoin3, cudaEventDisableTiming);
    }

    // main stream: init (weights + deg zero)
    init_kernel<<<(ninit + 255) / 256, 256>>>(W_e, W_h, N);
    cudaEventRecord(evFork, 0);

    // side stream s2: CSR build chain
    cudaStreamWaitEvent(s2, evFork, 0);
    count_kernel<<<(EP + 255) / 256, 256, 0, s2>>>(ei, E, EP);
    scan1_kernel<<<nsb, 256, 0, s2>>>(N);
    scan2_kernel<<<1, 256, 0, s2>>>(nsb);
    scan3_kernel<<<(N + 255) / 256, 256, 0, s2>>>(N, EP);
    scatter_kernel<<<(EP + 255) / 256, 256, 0, s2>>>(ei, E, EP);
    cudaEventRecord(evJoin2, s2);

    // side stream s3: hyperbolic node kernel (concurrent with node_e)
    cudaStreamWaitEvent(s3, evFork, 0);
    node_h_kernel<<<(N + 31) / 32, 128, 0, s3>>>(x_h, b_lin_h, att_h, N);
    cudaEventRecord(evJoin3, s3);

    // main stream: euclidean node kernel
    node_e_kernel<<<(N + 31) / 32, 128>>>(x_e, b_lin_e, att_e, N);

    // join all, then edge aggregation, then finalize
    cudaStreamWaitEvent(0, evJoin2, 0);
    cudaStreamWaitEvent(0, evJoin3, 0);
    edge_kernel<<<(N * 32 + 255) / 256, 256>>>(N);
    finalize_kernel<<<(N * 32 + 255) / 256, 256>>>(b_e, b_h, att_hf, att_ef, out, N);
}